// round 4
// baseline (speedup 1.0000x reference)
#include <cuda_runtime.h>
#include <cuda_bf16.h>
#include <math.h>

#define NMAX 100000
#define EMAX 3200000
#define GNUM 64
#define FIN  128

// -------- device scratch (float4-typed where vector-accessed => 16B aligned) ----
__device__ float4 g_h [(size_t)NMAX * 16];   // GEMM output per layer (max F=64)
__device__ float4 g_f [(size_t)NMAX * 16];   // layer output (next layer input)
__device__ float  g_dinv[NMAX];
__device__ int    g_deg [NMAX];
__device__ int    g_fill[NMAX];
__device__ int    g_rowptr[NMAX + 1];
__device__ int    g_src [EMAX];
__device__ int    g_dst [EMAX];
__device__ int    g_csrc[EMAX];              // CSR (by dst): source node per slot
__device__ float  g_ccoef[EMAX];             // CSR: dinv[src]*dinv[dst]
__device__ int    g_start[GNUM];
__device__ int    g_icnt [GNUM];
__device__ float  g_pool[GNUM * 32];

// -------- init --------
__global__ void k_init(int n) {
    int i = blockIdx.x * blockDim.x + threadIdx.x;
    if (i < n) { g_deg[i] = 0; g_fill[i] = 0; }
    if (i < GNUM) { g_icnt[i] = 0; g_start[i] = n; }
}

// -------- edge prep: int32 indices (JAX x64-disabled => int32), degree on dst ----
__global__ void k_prep(const int* __restrict__ ei, int E, int n) {
    int e = blockIdx.x * blockDim.x + threadIdx.x;
    if (e >= E) return;
    int s = ei[e];
    int d = ei[E + e];
    if ((unsigned)s >= (unsigned)n || (unsigned)d >= (unsigned)n) { s = 0; d = 0; }
    g_src[e] = s;
    g_dst[e] = d;
    atomicAdd(&g_deg[d], 1);
}

__global__ void k_dinv(int n) {
    int i = blockIdx.x * blockDim.x + threadIdx.x;
    if (i < n) g_dinv[i] = rsqrtf((float)g_deg[i] + 1.0f);
}

// -------- single-block exclusive scan of g_deg -> g_rowptr --------
__global__ void k_scan(int n) {
    __shared__ int sh[1024];
    int t = threadIdx.x;
    int carry = 0;
    for (int base = 0; base < n; base += 1024) {
        int v = (base + t < n) ? g_deg[base + t] : 0;
        sh[t] = v;
        __syncthreads();
        for (int off = 1; off < 1024; off <<= 1) {
            int a = (t >= off) ? sh[t - off] : 0;
            __syncthreads();
            sh[t] += a;
            __syncthreads();
        }
        if (base + t < n) g_rowptr[base + t] = carry + sh[t] - v;
        carry += sh[1023];
        __syncthreads();
    }
    if (t == 0) g_rowptr[n] = carry;
}

// -------- CSR fill (int atomics only) --------
__global__ void k_fill(int E) {
    int e = blockIdx.x * blockDim.x + threadIdx.x;
    if (e >= E) return;
    int s = g_src[e], d = g_dst[e];
    int pos = g_rowptr[d] + atomicAdd(&g_fill[d], 1);
    g_csrc[pos]  = s;
    g_ccoef[pos] = g_dinv[s] * g_dinv[d];
}

// -------- graph boundaries (batch sorted, int32) --------
__global__ void k_bound(const int* __restrict__ batch, int n) {
    int i = blockIdx.x * blockDim.x + threadIdx.x;
    if (i >= n) return;
    int b = batch[i];
    if ((unsigned)b >= GNUM) return;
    atomicAdd(&g_icnt[b], 1);
    if (i == 0 || batch[i - 1] != b) atomicMin(&g_start[b], i);
}

// -------- tiled GEMM: g_h[n,MOUT] = X[n,K] @ W[K,MOUT]; blockDim = NB*MOUT ----
template<int K, int MOUT, int NB>
__global__ void k_gemm(const float* __restrict__ X, const float* __restrict__ W, int n) {
    __shared__ float Ws[K * MOUT];
    __shared__ float Xs[NB * K];
    const int T = NB * MOUT;
    int tid = threadIdx.x;
    for (int i = tid; i < K * MOUT; i += T) Ws[i] = W[i];
    int base = blockIdx.x * NB;
    for (int i = tid; i < NB * K; i += T) {
        int node = base + i / K;
        Xs[i] = (node < n) ? X[(size_t)node * K + (i % K)] : 0.f;
    }
    __syncthreads();
    int nl = tid / MOUT, m = tid % MOUT;
    int node = base + nl;
    if (node < n) {
        float acc = 0.f;
        #pragma unroll
        for (int k = 0; k < K; k++) acc += Xs[nl * K + k] * Ws[k * MOUT + m];
        ((float*)g_h)[(size_t)node * MOUT + m] = acc;
    }
}

// -------- gather aggregation + self-loop + bias (+relu) : g_f = GCNConv(g_h) ----
template<int F4, bool RELU>   // F4 = F/4, power of 2
__global__ void k_gather(const float* __restrict__ bias, int n) {
    int idx = blockIdx.x * blockDim.x + threadIdx.x;
    if (idx >= n * F4) return;
    int i = idx / F4, g = idx & (F4 - 1);
    int beg = g_rowptr[i], end = g_rowptr[i + 1];
    float4 acc = make_float4(0.f, 0.f, 0.f, 0.f);
    for (int j = beg; j < end; j++) {
        int   s = __ldg(&g_csrc[j]);
        float c = __ldg(&g_ccoef[j]);
        float4 v = g_h[(size_t)s * F4 + g];
        acc.x += v.x * c; acc.y += v.y * c; acc.z += v.z * c; acc.w += v.w * c;
    }
    float di = g_dinv[i];
    float d2 = di * di;
    float4 hv = g_h[(size_t)i * F4 + g];
    float bx = __ldg(&bias[4 * g + 0]), by = __ldg(&bias[4 * g + 1]);
    float bz = __ldg(&bias[4 * g + 2]), bw = __ldg(&bias[4 * g + 3]);
    float rx = acc.x + hv.x * d2 + bx;
    float ry = acc.y + hv.y * d2 + by;
    float rz = acc.z + hv.z * d2 + bz;
    float rw = acc.w + hv.w * d2 + bw;
    if (RELU) {
        rx = fmaxf(rx, 0.f); ry = fmaxf(ry, 0.f);
        rz = fmaxf(rz, 0.f); rw = fmaxf(rw, 0.f);
    }
    g_f[(size_t)i * F4 + g] = make_float4(rx, ry, rz, rw);
}

// -------- mean pool: one block per graph (batch sorted => contiguous range) ----
__global__ void k_pool(int n) {
    int g = blockIdx.x;
    int t = threadIdx.x;          // 256 threads
    int f = t & 31, p = t >> 5;   // 8 partials per feature
    int cnt = g_icnt[g];
    int beg = g_start[g];
    const float* fsrc = (const float*)g_f;
    float s = 0.f;
    for (int k = p; k < cnt; k += 8)
        s += fsrc[(size_t)(beg + k) * 32 + f];
    __shared__ float sh[256];
    sh[t] = s;
    __syncthreads();
    if (p == 0) {
        float tot = 0.f;
        #pragma unroll
        for (int q = 0; q < 8; q++) tot += sh[q * 32 + f];
        g_pool[g * 32 + f] = tot / fmaxf((float)cnt, 1.f);
    }
}

// -------- MLP head --------
__global__ void k_head(const float* __restrict__ Wa, const float* __restrict__ ba,
                       const float* __restrict__ Wo, const float* __restrict__ bo,
                       float* __restrict__ out) {
    __shared__ float a[64];
    __shared__ float ps[32];
    int g = blockIdx.x, t = threadIdx.x;
    if (t < 32) ps[t] = g_pool[g * 32 + t];
    __syncthreads();
    float acc = ba[t];
    #pragma unroll
    for (int k = 0; k < 32; k++) acc += ps[k] * Wa[k * 64 + t];
    a[t] = fmaxf(acc, 0.f);
    __syncthreads();
    if (t < 32) {
        float o = bo[t];
        #pragma unroll
        for (int k = 0; k < 64; k++) o += a[k] * Wo[k * 32 + t];
        out[g * 32 + t] = tanhf(o);
    }
}

// ============================================================================
extern "C" void kernel_launch(void* const* d_in, const int* in_sizes, int n_in,
                              void* d_out, int out_size) {
    const float* x     = (const float*)d_in[0];
    const int*   ei    = (const int*)d_in[1];    // int32 (JAX default, x64 disabled)
    const int*   batch = (const int*)d_in[2];    // int32
    const float* W1 = (const float*)d_in[3];  const float* b1 = (const float*)d_in[4];
    const float* W2 = (const float*)d_in[5];  const float* b2 = (const float*)d_in[6];
    const float* W3 = (const float*)d_in[7];  const float* b3 = (const float*)d_in[8];
    const float* Wa = (const float*)d_in[9];  const float* ba = (const float*)d_in[10];
    const float* Wo = (const float*)d_in[11]; const float* bo = (const float*)d_in[12];
    float* out = (float*)d_out;

    int N = in_sizes[0] / FIN;
    int E = in_sizes[1] / 2;
    if (N > NMAX) N = NMAX;
    if (E > EMAX) E = EMAX;

    void* p_f = nullptr;
    cudaGetSymbolAddress(&p_f, g_f);

    const int TB = 256;
    auto blocks = [](long long work, int tb) { return (int)((work + tb - 1) / tb); };

    // ---- CSR build + norm coefficients (shared by all 3 layers) ----
    k_init<<<blocks(N, TB), TB>>>(N);
    k_prep<<<blocks(E, TB), TB>>>(ei, E, N);
    k_dinv<<<blocks(N, TB), TB>>>(N);
    k_scan<<<1, 1024>>>(N);
    k_fill<<<blocks(E, TB), TB>>>(E);
    k_bound<<<blocks(N, TB), TB>>>(batch, N);

    // ---- layer 1: 128 -> 16 ----
    k_gemm<128, 16, 16><<<blocks(N, 16), 16 * 16>>>(x, W1, N);
    k_gather<4, true><<<blocks((long long)N * 4, TB), TB>>>(b1, N);

    // ---- layer 2: 16 -> 64 ----
    k_gemm<16, 64, 4><<<blocks(N, 4), 4 * 64>>>((const float*)p_f, W2, N);
    k_gather<16, true><<<blocks((long long)N * 16, TB), TB>>>(b2, N);

    // ---- layer 3: 64 -> 32 ----
    k_gemm<64, 32, 8><<<blocks(N, 8), 8 * 32>>>((const float*)p_f, W3, N);
    k_gather<8, false><<<blocks((long long)N * 8, TB), TB>>>(b3, N);

    // ---- pool + head ----
    k_pool<<<GNUM, 256>>>(N);
    k_head<<<GNUM, 64>>>(Wa, ba, Wo, bo, out);
}

// round 5
// speedup vs baseline: 1.2916x; 1.2916x over previous
#include <cuda_runtime.h>
#include <cuda_bf16.h>
#include <math.h>

#define NMAX 100000
#define EMAX 3200000
#define GNUM 64
#define FIN  128
#define SCB  1024                      // scan block size
#define NBLK ((NMAX + SCB - 1) / SCB)  // 98 partial blocks

// -------- device scratch (float4-typed where vector-accessed => 16B aligned) ----
__device__ float4 g_A [(size_t)NMAX * 16];   // ping buffer (max F=64)
__device__ float4 g_B [(size_t)NMAX * 16];   // pong buffer
__device__ float  g_dinv[NMAX];
__device__ int    g_deg [NMAX];
__device__ int    g_fill[NMAX];
__device__ int    g_rowptr[NMAX + 1];
__device__ int    g_bsum[NBLK];              // per-block scan partial sums
__device__ int    g_boff[NBLK];              // scanned block offsets
__device__ int    g_src [EMAX];
__device__ int    g_dst [EMAX];
__device__ int    g_csrc[EMAX];              // CSR (by dst): source node per slot
__device__ float  g_ccoef[EMAX];             // CSR: dinv[src]*dinv[dst]
__device__ int    g_start[GNUM];
__device__ int    g_icnt [GNUM];
__device__ float  g_pool[GNUM * 32];

// -------- init --------
__global__ void k_init(int n) {
    int i = blockIdx.x * blockDim.x + threadIdx.x;
    if (i < n) { g_deg[i] = 0; g_fill[i] = 0; }
    if (i < GNUM) { g_icnt[i] = 0; g_start[i] = n; }
}

// -------- edge prep: int32 indices, degree count on dst --------
__global__ void k_prep(const int* __restrict__ ei, int E, int n) {
    int e = blockIdx.x * blockDim.x + threadIdx.x;
    if (e >= E) return;
    int s = ei[e];
    int d = ei[E + e];
    if ((unsigned)s >= (unsigned)n || (unsigned)d >= (unsigned)n) { s = 0; d = 0; }
    g_src[e] = s;
    g_dst[e] = d;
    atomicAdd(&g_deg[d], 1);
}

__global__ void k_dinv(int n) {
    int i = blockIdx.x * blockDim.x + threadIdx.x;
    if (i < n) g_dinv[i] = rsqrtf((float)g_deg[i] + 1.0f);
}

// -------- phase 1: block-local exclusive scan of g_deg (shfl-based) --------
__global__ void k_scan1(int n) {
    __shared__ int wsum[32];
    int t = threadIdx.x, lane = t & 31, w = t >> 5;
    int i = blockIdx.x * SCB + t;
    int v = (i < n) ? g_deg[i] : 0;
    int inc = v;
    #pragma unroll
    for (int o = 1; o < 32; o <<= 1) {
        int u = __shfl_up_sync(0xffffffffu, inc, o);
        if (lane >= o) inc += u;
    }
    if (lane == 31) wsum[w] = inc;
    __syncthreads();
    if (w == 0) {
        int s = wsum[lane];
        int sinc = s;
        #pragma unroll
        for (int o = 1; o < 32; o <<= 1) {
            int u = __shfl_up_sync(0xffffffffu, sinc, o);
            if (lane >= o) sinc += u;
        }
        wsum[lane] = sinc - s;           // exclusive warp offsets
        if (lane == 31) g_bsum[blockIdx.x] = sinc;  // block total
    }
    __syncthreads();
    if (i < n) g_rowptr[i] = wsum[w] + inc - v;      // block-local exclusive
}

// -------- phase 2: single small block scans the <=1024 block sums --------
__global__ void k_scan2(int nb, int n) {
    __shared__ int wsum[32];
    int t = threadIdx.x, lane = t & 31, w = t >> 5;
    int v = (t < nb) ? g_bsum[t] : 0;
    int inc = v;
    #pragma unroll
    for (int o = 1; o < 32; o <<= 1) {
        int u = __shfl_up_sync(0xffffffffu, inc, o);
        if (lane >= o) inc += u;
    }
    if (lane == 31) wsum[w] = inc;
    __syncthreads();
    if (w == 0) {
        int s = wsum[lane];
        int sinc = s;
        #pragma unroll
        for (int o = 1; o < 32; o <<= 1) {
            int u = __shfl_up_sync(0xffffffffu, sinc, o);
            if (lane >= o) sinc += u;
        }
        wsum[lane] = sinc - s;
        if (lane == 31) g_rowptr[n] = sinc;          // grand total = E
    }
    __syncthreads();
    if (t < nb) g_boff[t] = wsum[w] + inc - v;
}

// -------- phase 3: add block offsets --------
__global__ void k_scan3(int n) {
    int i = blockIdx.x * blockDim.x + threadIdx.x;
    if (i < n) g_rowptr[i] += g_boff[i / SCB];
}

// -------- CSR fill (int atomics only) --------
__global__ void k_fill(int E) {
    int e = blockIdx.x * blockDim.x + threadIdx.x;
    if (e >= E) return;
    int s = g_src[e], d = g_dst[e];
    int pos = g_rowptr[d] + atomicAdd(&g_fill[d], 1);
    g_csrc[pos]  = s;
    g_ccoef[pos] = g_dinv[s] * g_dinv[d];
}

// -------- graph boundaries (batch sorted, int32) --------
__global__ void k_bound(const int* __restrict__ batch, int n) {
    int i = blockIdx.x * blockDim.x + threadIdx.x;
    if (i >= n) return;
    int b = batch[i];
    if ((unsigned)b >= GNUM) return;
    atomicAdd(&g_icnt[b], 1);
    if (i == 0 || batch[i - 1] != b) atomicMin(&g_start[b], i);
}

// -------- tiled GEMM: OUT[n,MOUT] = X[n,K] @ W[K,MOUT] (+bias,relu if EPI) ----
template<int K, int MOUT, int NB, bool EPI>
__global__ void k_gemm(const float* __restrict__ X, const float* __restrict__ W,
                       const float* __restrict__ bias, float* __restrict__ OUT, int n) {
    __shared__ float Ws[K * MOUT];
    __shared__ float Xs[NB * K];
    const int T = NB * MOUT;
    int tid = threadIdx.x;
    for (int i = tid; i < K * MOUT; i += T) Ws[i] = W[i];
    int base = blockIdx.x * NB;
    for (int i = tid; i < NB * K; i += T) {
        int node = base + i / K;
        Xs[i] = (node < n) ? X[(size_t)node * K + (i % K)] : 0.f;
    }
    __syncthreads();
    int nl = tid / MOUT, m = tid % MOUT;
    int node = base + nl;
    if (node < n) {
        float acc = 0.f;
        #pragma unroll
        for (int k = 0; k < K; k++) acc += Xs[nl * K + k] * Ws[k * MOUT + m];
        if (EPI) acc = fmaxf(acc + __ldg(&bias[m]), 0.f);
        OUT[(size_t)node * MOUT + m] = acc;
    }
}

// -------- gather: dst = Â src  (+bias)(+relu); Â includes self-loop ----------
template<int F4, bool RELU, bool HASB>  // F4 = F/4, power of 2
__global__ void k_gather(const float4* __restrict__ src, float4* __restrict__ dst,
                         const float* __restrict__ bias, int n) {
    int idx = blockIdx.x * blockDim.x + threadIdx.x;
    if (idx >= n * F4) return;
    int i = idx / F4, g = idx & (F4 - 1);
    int beg = g_rowptr[i], end = g_rowptr[i + 1];
    float4 acc = make_float4(0.f, 0.f, 0.f, 0.f);
    for (int j = beg; j < end; j++) {
        int   s = __ldg(&g_csrc[j]);
        float c = __ldg(&g_ccoef[j]);
        float4 v = src[(size_t)s * F4 + g];
        acc.x += v.x * c; acc.y += v.y * c; acc.z += v.z * c; acc.w += v.w * c;
    }
    float di = g_dinv[i];
    float d2 = di * di;
    float4 hv = src[(size_t)i * F4 + g];
    float rx = acc.x + hv.x * d2;
    float ry = acc.y + hv.y * d2;
    float rz = acc.z + hv.z * d2;
    float rw = acc.w + hv.w * d2;
    if (HASB) {
        rx += __ldg(&bias[4 * g + 0]); ry += __ldg(&bias[4 * g + 1]);
        rz += __ldg(&bias[4 * g + 2]); rw += __ldg(&bias[4 * g + 3]);
    }
    if (RELU) {
        rx = fmaxf(rx, 0.f); ry = fmaxf(ry, 0.f);
        rz = fmaxf(rz, 0.f); rw = fmaxf(rw, 0.f);
    }
    dst[(size_t)i * F4 + g] = make_float4(rx, ry, rz, rw);
}

// -------- mean pool: one block per graph (batch sorted => contiguous range) ----
__global__ void k_pool(const float* __restrict__ fsrc) {
    int g = blockIdx.x;
    int t = threadIdx.x;          // 256 threads
    int f = t & 31, p = t >> 5;   // 8 partials per feature
    int cnt = g_icnt[g];
    int beg = g_start[g];
    float s = 0.f;
    for (int k = p; k < cnt; k += 8)
        s += fsrc[(size_t)(beg + k) * 32 + f];
    __shared__ float sh[256];
    sh[t] = s;
    __syncthreads();
    if (p == 0) {
        float tot = 0.f;
        #pragma unroll
        for (int q = 0; q < 8; q++) tot += sh[q * 32 + f];
        g_pool[g * 32 + f] = tot / fmaxf((float)cnt, 1.f);
    }
}

// -------- MLP head --------
__global__ void k_head(const float* __restrict__ Wa, const float* __restrict__ ba,
                       const float* __restrict__ Wo, const float* __restrict__ bo,
                       float* __restrict__ out) {
    __shared__ float a[64];
    __shared__ float ps[32];
    int g = blockIdx.x, t = threadIdx.x;
    if (t < 32) ps[t] = g_pool[g * 32 + t];
    __syncthreads();
    float acc = ba[t];
    #pragma unroll
    for (int k = 0; k < 32; k++) acc += ps[k] * Wa[k * 64 + t];
    a[t] = fmaxf(acc, 0.f);
    __syncthreads();
    if (t < 32) {
        float o = bo[t];
        #pragma unroll
        for (int k = 0; k < 64; k++) o += a[k] * Wo[k * 32 + t];
        out[g * 32 + t] = tanhf(o);
    }
}

// ============================================================================
extern "C" void kernel_launch(void* const* d_in, const int* in_sizes, int n_in,
                              void* d_out, int out_size) {
    const float* x     = (const float*)d_in[0];
    const int*   ei    = (const int*)d_in[1];    // int32 (JAX default, x64 off)
    const int*   batch = (const int*)d_in[2];
    const float* W1 = (const float*)d_in[3];  const float* b1 = (const float*)d_in[4];
    const float* W2 = (const float*)d_in[5];  const float* b2 = (const float*)d_in[6];
    const float* W3 = (const float*)d_in[7];  const float* b3 = (const float*)d_in[8];
    const float* Wa = (const float*)d_in[9];  const float* ba = (const float*)d_in[10];
    const float* Wo = (const float*)d_in[11]; const float* bo = (const float*)d_in[12];
    float* out = (float*)d_out;

    int N = in_sizes[0] / FIN;
    int E = in_sizes[1] / 2;
    if (N > NMAX) N = NMAX;
    if (E > EMAX) E = EMAX;
    int nb = (N + SCB - 1) / SCB;

    void *pA = nullptr, *pB = nullptr;
    cudaGetSymbolAddress(&pA, g_A);
    cudaGetSymbolAddress(&pB, g_B);
    float4* A4 = (float4*)pA;  float* Af = (float*)pA;
    float4* B4 = (float4*)pB;  float* Bf = (float*)pB;

    const int TB = 256;
    auto blocks = [](long long work, int tb) { return (int)((work + tb - 1) / tb); };

    // ---- CSR build + norm coefficients (shared by all 3 layers) ----
    k_init<<<blocks(N, TB), TB>>>(N);
    k_prep<<<blocks(E, TB), TB>>>(ei, E, N);
    k_dinv<<<blocks(N, TB), TB>>>(N);
    k_scan1<<<nb, SCB>>>(N);
    k_scan2<<<1, SCB>>>(nb, N);
    k_scan3<<<blocks(N, TB), TB>>>(N);
    k_fill<<<blocks(E, TB), TB>>>(E);
    k_bound<<<blocks(N, TB), TB>>>(batch, N);

    // ---- layer 1: h1 = relu(Â(x@W1) + b1)   [aggregate in 16-dim] ----
    k_gemm<128, 16, 16, false><<<blocks(N, 16), 16 * 16>>>(x, W1, nullptr, Af, N);
    k_gather<4, true, true><<<blocks((long long)N * 4, TB), TB>>>(A4, B4, b1, N);

    // ---- layer 2: h2 = relu((Â h1)@W2 + b2) [aggregate in 16-dim, then GEMM] ----
    k_gather<4, false, false><<<blocks((long long)N * 4, TB), TB>>>(B4, A4, nullptr, N);
    k_gemm<16, 64, 4, true><<<blocks(N, 4), 4 * 64>>>(Af, W2, b2, Bf, N);

    // ---- layer 3: h3 = Â(h2@W3) + b3        [aggregate in 32-dim] ----
    k_gemm<64, 32, 8, false><<<blocks(N, 8), 8 * 32>>>(Bf, W3, nullptr, Af, N);
    k_gather<8, false, true><<<blocks((long long)N * 8, TB), TB>>>(A4, B4, b3, N);

    // ---- pool + head ----
    k_pool<<<GNUM, 256>>>(Bf);
    k_head<<<GNUM, 64>>>(Wa, ba, Wo, bo, out);
}

// round 6
// speedup vs baseline: 1.3105x; 1.0147x over previous
#include <cuda_runtime.h>
#include <cuda_bf16.h>
#include <math.h>

#define NMAX 100000
#define EMAX 3200000
#define GNUM 64
#define FIN  128
#define SCB  1024
#define NBLK ((NMAX + SCB - 1) / SCB)

// -------- device scratch --------
__device__ float4 g_A [(size_t)NMAX * 16];   // ping (max F=64)
__device__ float4 g_B [(size_t)NMAX * 16];   // pong
__device__ float  g_dinv[NMAX];
__device__ int    g_deg [NMAX];
__device__ int    g_fill[NMAX];
__device__ int    g_rowptr[NMAX + 1];
__device__ int    g_bsum[NBLK];
__device__ int    g_boff[NBLK];
__device__ int    g_csrc[EMAX];              // CSR (by dst): source node per slot
__device__ int    g_start[GNUM];
__device__ int    g_icnt [GNUM];
__device__ float  g_pool[GNUM * 32];

// -------- init --------
__global__ void k_init(int n) {
    int i = blockIdx.x * blockDim.x + threadIdx.x;
    if (i < n) { g_deg[i] = 0; g_fill[i] = 0; }
    if (i < GNUM) { g_icnt[i] = 0; g_start[i] = n; }
}

// -------- degree count on dst --------
__global__ void k_prep(const int* __restrict__ ei, int E, int n) {
    int e = blockIdx.x * blockDim.x + threadIdx.x;
    if (e >= E) return;
    int d = ei[E + e];
    if ((unsigned)d >= (unsigned)n) d = 0;
    atomicAdd(&g_deg[d], 1);
}

__global__ void k_dinv(int n) {
    int i = blockIdx.x * blockDim.x + threadIdx.x;
    if (i < n) g_dinv[i] = rsqrtf((float)g_deg[i] + 1.0f);
}

// -------- 3-phase exclusive scan of g_deg -> g_rowptr --------
__global__ void k_scan1(int n) {
    __shared__ int wsum[32];
    int t = threadIdx.x, lane = t & 31, w = t >> 5;
    int i = blockIdx.x * SCB + t;
    int v = (i < n) ? g_deg[i] : 0;
    int inc = v;
    #pragma unroll
    for (int o = 1; o < 32; o <<= 1) {
        int u = __shfl_up_sync(0xffffffffu, inc, o);
        if (lane >= o) inc += u;
    }
    if (lane == 31) wsum[w] = inc;
    __syncthreads();
    if (w == 0) {
        int s = wsum[lane];
        int sinc = s;
        #pragma unroll
        for (int o = 1; o < 32; o <<= 1) {
            int u = __shfl_up_sync(0xffffffffu, sinc, o);
            if (lane >= o) sinc += u;
        }
        wsum[lane] = sinc - s;
        if (lane == 31) g_bsum[blockIdx.x] = sinc;
    }
    __syncthreads();
    if (i < n) g_rowptr[i] = wsum[w] + inc - v;
}

__global__ void k_scan2(int nb, int n) {
    __shared__ int wsum[32];
    int t = threadIdx.x, lane = t & 31, w = t >> 5;
    int v = (t < nb) ? g_bsum[t] : 0;
    int inc = v;
    #pragma unroll
    for (int o = 1; o < 32; o <<= 1) {
        int u = __shfl_up_sync(0xffffffffu, inc, o);
        if (lane >= o) inc += u;
    }
    if (lane == 31) wsum[w] = inc;
    __syncthreads();
    if (w == 0) {
        int s = wsum[lane];
        int sinc = s;
        #pragma unroll
        for (int o = 1; o < 32; o <<= 1) {
            int u = __shfl_up_sync(0xffffffffu, sinc, o);
            if (lane >= o) sinc += u;
        }
        wsum[lane] = sinc - s;
        if (lane == 31) g_rowptr[n] = sinc;
    }
    __syncthreads();
    if (t < nb) g_boff[t] = wsum[w] + inc - v;
}

__global__ void k_scan3(int n) {
    int i = blockIdx.x * blockDim.x + threadIdx.x;
    if (i < n) g_rowptr[i] += g_boff[i / SCB];
}

// -------- CSR fill: only source index (coef factorized away) --------
__global__ void k_fill(const int* __restrict__ ei, int E, int n) {
    int e = blockIdx.x * blockDim.x + threadIdx.x;
    if (e >= E) return;
    int s = ei[e];
    int d = ei[E + e];
    if ((unsigned)s >= (unsigned)n || (unsigned)d >= (unsigned)n) { s = 0; d = 0; }
    int pos = g_rowptr[d] + atomicAdd(&g_fill[d], 1);
    g_csrc[pos] = s;
}

// -------- graph boundaries (batch sorted, int32) --------
__global__ void k_bound(const int* __restrict__ batch, int n) {
    int i = blockIdx.x * blockDim.x + threadIdx.x;
    if (i >= n) return;
    int b = batch[i];
    if ((unsigned)b >= GNUM) return;
    atomicAdd(&g_icnt[b], 1);
    if (i == 0 || batch[i - 1] != b) atomicMin(&g_start[b], i);
}

// -------- tiled GEMM: OUT = X@W, epilogue: optional bias+relu, optional *dinv ----
template<int K, int MOUT, int NB, bool BIASRELU, bool SCALE>
__global__ void k_gemm(const float* __restrict__ X, const float* __restrict__ W,
                       const float* __restrict__ bias, float* __restrict__ OUT, int n) {
    __shared__ float Ws[K * MOUT];
    __shared__ float Xs[NB * K];
    const int T = NB * MOUT;
    int tid = threadIdx.x;
    for (int i = tid; i < K * MOUT; i += T) Ws[i] = W[i];
    int base = blockIdx.x * NB;
    for (int i = tid; i < NB * K; i += T) {
        int node = base + i / K;
        Xs[i] = (node < n) ? X[(size_t)node * K + (i % K)] : 0.f;
    }
    __syncthreads();
    int nl = tid / MOUT, m = tid % MOUT;
    int node = base + nl;
    if (node < n) {
        float acc = 0.f;
        #pragma unroll
        for (int k = 0; k < K; k++) acc += Xs[nl * K + k] * Ws[k * MOUT + m];
        if (BIASRELU) acc = fmaxf(acc + __ldg(&bias[m]), 0.f);
        if (SCALE) acc *= g_dinv[node];
        OUT[(size_t)node * MOUT + m] = acc;
    }
}

// -------- warp-per-node gather: dst_i = dinv_i*(sum_{nbr} src + src_i) [+b][relu][*dinv] --
template<int F4, bool RELU, bool HASB, bool SCALEOUT>  // F4 in {4,8}
__global__ void k_gatherw(const float4* __restrict__ src, float4* __restrict__ dst,
                          const float* __restrict__ bias, int n) {
    int wid = (blockIdx.x * blockDim.x + threadIdx.x) >> 5;
    if (wid >= n) return;
    const int EPW = 32 / F4;
    int lane = threadIdx.x & 31;
    int e_l = lane / F4;          // edge slot within warp
    int g   = lane & (F4 - 1);    // feature group
    int beg = g_rowptr[wid], end = g_rowptr[wid + 1];
    float4 acc = make_float4(0.f, 0.f, 0.f, 0.f);
    for (int j = beg + e_l; j < end; j += EPW) {
        int s = __ldg(&g_csrc[j]);
        float4 v = __ldg(&src[(size_t)s * F4 + g]);
        acc.x += v.x; acc.y += v.y; acc.z += v.z; acc.w += v.w;
    }
    #pragma unroll
    for (int off = 16; off >= F4; off >>= 1) {
        acc.x += __shfl_xor_sync(0xffffffffu, acc.x, off);
        acc.y += __shfl_xor_sync(0xffffffffu, acc.y, off);
        acc.z += __shfl_xor_sync(0xffffffffu, acc.z, off);
        acc.w += __shfl_xor_sync(0xffffffffu, acc.w, off);
    }
    if (lane < F4) {
        float di = g_dinv[wid];
        float4 hv = src[(size_t)wid * F4 + g];
        float rx = (acc.x + hv.x) * di;
        float ry = (acc.y + hv.y) * di;
        float rz = (acc.z + hv.z) * di;
        float rw = (acc.w + hv.w) * di;
        if (HASB) {
            rx += __ldg(&bias[4 * g + 0]); ry += __ldg(&bias[4 * g + 1]);
            rz += __ldg(&bias[4 * g + 2]); rw += __ldg(&bias[4 * g + 3]);
        }
        if (RELU) {
            rx = fmaxf(rx, 0.f); ry = fmaxf(ry, 0.f);
            rz = fmaxf(rz, 0.f); rw = fmaxf(rw, 0.f);
        }
        if (SCALEOUT) { rx *= di; ry *= di; rz *= di; rw *= di; }
        dst[(size_t)wid * F4 + g] = make_float4(rx, ry, rz, rw);
    }
}

// -------- mean pool (batch sorted => contiguous ranges) --------
__global__ void k_pool(const float* __restrict__ fsrc) {
    int g = blockIdx.x;
    int t = threadIdx.x;
    int f = t & 31, p = t >> 5;
    int cnt = g_icnt[g];
    int beg = g_start[g];
    float s = 0.f;
    for (int k = p; k < cnt; k += 8)
        s += fsrc[(size_t)(beg + k) * 32 + f];
    __shared__ float sh[256];
    sh[t] = s;
    __syncthreads();
    if (p == 0) {
        float tot = 0.f;
        #pragma unroll
        for (int q = 0; q < 8; q++) tot += sh[q * 32 + f];
        g_pool[g * 32 + f] = tot / fmaxf((float)cnt, 1.f);
    }
}

// -------- MLP head --------
__global__ void k_head(const float* __restrict__ Wa, const float* __restrict__ ba,
                       const float* __restrict__ Wo, const float* __restrict__ bo,
                       float* __restrict__ out) {
    __shared__ float a[64];
    __shared__ float ps[32];
    int g = blockIdx.x, t = threadIdx.x;
    if (t < 32) ps[t] = g_pool[g * 32 + t];
    __syncthreads();
    float acc = ba[t];
    #pragma unroll
    for (int k = 0; k < 32; k++) acc += ps[k] * Wa[k * 64 + t];
    a[t] = fmaxf(acc, 0.f);
    __syncthreads();
    if (t < 32) {
        float o = bo[t];
        #pragma unroll
        for (int k = 0; k < 64; k++) o += a[k] * Wo[k * 32 + t];
        out[g * 32 + t] = tanhf(o);
    }
}

// ============================================================================
extern "C" void kernel_launch(void* const* d_in, const int* in_sizes, int n_in,
                              void* d_out, int out_size) {
    const float* x     = (const float*)d_in[0];
    const int*   ei    = (const int*)d_in[1];
    const int*   batch = (const int*)d_in[2];
    const float* W1 = (const float*)d_in[3];  const float* b1 = (const float*)d_in[4];
    const float* W2 = (const float*)d_in[5];  const float* b2 = (const float*)d_in[6];
    const float* W3 = (const float*)d_in[7];  const float* b3 = (const float*)d_in[8];
    const float* Wa = (const float*)d_in[9];  const float* ba = (const float*)d_in[10];
    const float* Wo = (const float*)d_in[11]; const float* bo = (const float*)d_in[12];
    float* out = (float*)d_out;

    int N = in_sizes[0] / FIN;
    int E = in_sizes[1] / 2;
    if (N > NMAX) N = NMAX;
    if (E > EMAX) E = EMAX;
    int nb = (N + SCB - 1) / SCB;

    void *pA = nullptr, *pB = nullptr;
    cudaGetSymbolAddress(&pA, g_A);
    cudaGetSymbolAddress(&pB, g_B);
    float4* A4 = (float4*)pA;  float* Af = (float*)pA;
    float4* B4 = (float4*)pB;  float* Bf = (float*)pB;

    const int TB = 256;
    auto blocks = [](long long work, int tb) { return (int)((work + tb - 1) / tb); };
    int gw = blocks((long long)N * 32, TB);   // warp-per-node gather grid

    // ---- CSR build + dinv (shared by all 3 layers) ----
    k_init<<<blocks(N, TB), TB>>>(N);
    k_prep<<<blocks(E, TB), TB>>>(ei, E, N);
    k_dinv<<<blocks(N, TB), TB>>>(N);
    k_scan1<<<nb, SCB>>>(N);
    k_scan2<<<1, SCB>>>(nb, N);
    k_scan3<<<blocks(N, TB), TB>>>(N);
    k_fill<<<blocks(E, TB), TB>>>(ei, E, N);
    k_bound<<<blocks(N, TB), TB>>>(batch, N);

    // ---- layer 1: z1s = dinv*(x@W1); h1s = dinv*relu(dinv*(Σ z1s) + b1) ----
    k_gemm<128, 16, 16, false, true><<<blocks(N, 16), 16 * 16>>>(x, W1, nullptr, Af, N);
    k_gatherw<4, true, true, true><<<gw, TB>>>(A4, B4, b1, N);

    // ---- layer 2: agg2 = dinv*(Σ h1s); h2 = relu(agg2@W2 + b2) ----
    k_gatherw<4, false, false, false><<<gw, TB>>>(B4, A4, nullptr, N);
    k_gemm<16, 64, 4, true, false><<<blocks(N, 4), 4 * 64>>>(Af, W2, b2, Bf, N);

    // ---- layer 3: z3s = dinv*(h2@W3); h3 = dinv*(Σ z3s) + b3 ----
    k_gemm<64, 32, 8, false, true><<<blocks(N, 8), 8 * 32>>>(Bf, W3, nullptr, Af, N);
    k_gatherw<8, false, true, false><<<gw, TB>>>(A4, B4, b3, N);

    // ---- pool + head ----
    k_pool<<<GNUM, 256>>>(Bf);
    k_head<<<GNUM, 64>>>(Wa, ba, Wo, bo, out);
}

// round 7
// speedup vs baseline: 1.6416x; 1.2527x over previous
#include <cuda_runtime.h>
#include <cuda_bf16.h>
#include <math.h>

#define NMAX 100000
#define EMAX 3200000
#define GNUM 64
#define FIN  128
#define SCB  1024
#define NBLK ((NMAX + SCB - 1) / SCB)

// -------- device scratch --------
__device__ float4 g_A [(size_t)NMAX * 16];   // ping (max F=64)
__device__ float4 g_B [(size_t)NMAX * 16];   // pong
__device__ float  g_dinv[NMAX];
__device__ int    g_deg [NMAX];
__device__ int    g_fill[NMAX];
__device__ int    g_rowptr[NMAX + 1];
__device__ int    g_bsum[NBLK];
__device__ int    g_boff[NBLK];
__device__ int    g_csrc[EMAX];              // CSR (by dst): source node per slot
__device__ int    g_start[GNUM];
__device__ int    g_icnt [GNUM];
__device__ float  g_pool[GNUM * 32];

// -------- init --------
__global__ void k_init(int n) {
    int i = blockIdx.x * blockDim.x + threadIdx.x;
    if (i < n) { g_deg[i] = 0; g_fill[i] = 0; }
    if (i < GNUM) { g_icnt[i] = 0; g_start[i] = n; }
}

// -------- degree count on dst --------
__global__ void k_prep(const int* __restrict__ ei, int E, int n) {
    int e = blockIdx.x * blockDim.x + threadIdx.x;
    if (e >= E) return;
    int d = ei[E + e];
    if ((unsigned)d >= (unsigned)n) d = 0;
    atomicAdd(&g_deg[d], 1);
}

__global__ void k_dinv(int n) {
    int i = blockIdx.x * blockDim.x + threadIdx.x;
    if (i < n) g_dinv[i] = rsqrtf((float)g_deg[i] + 1.0f);
}

// -------- 3-phase exclusive scan of g_deg -> g_rowptr --------
__global__ void k_scan1(int n) {
    __shared__ int wsum[32];
    int t = threadIdx.x, lane = t & 31, w = t >> 5;
    int i = blockIdx.x * SCB + t;
    int v = (i < n) ? g_deg[i] : 0;
    int inc = v;
    #pragma unroll
    for (int o = 1; o < 32; o <<= 1) {
        int u = __shfl_up_sync(0xffffffffu, inc, o);
        if (lane >= o) inc += u;
    }
    if (lane == 31) wsum[w] = inc;
    __syncthreads();
    if (w == 0) {
        int s = wsum[lane];
        int sinc = s;
        #pragma unroll
        for (int o = 1; o < 32; o <<= 1) {
            int u = __shfl_up_sync(0xffffffffu, sinc, o);
            if (lane >= o) sinc += u;
        }
        wsum[lane] = sinc - s;
        if (lane == 31) g_bsum[blockIdx.x] = sinc;
    }
    __syncthreads();
    if (i < n) g_rowptr[i] = wsum[w] + inc - v;
}

__global__ void k_scan2(int nb, int n) {
    __shared__ int wsum[32];
    int t = threadIdx.x, lane = t & 31, w = t >> 5;
    int v = (t < nb) ? g_bsum[t] : 0;
    int inc = v;
    #pragma unroll
    for (int o = 1; o < 32; o <<= 1) {
        int u = __shfl_up_sync(0xffffffffu, inc, o);
        if (lane >= o) inc += u;
    }
    if (lane == 31) wsum[w] = inc;
    __syncthreads();
    if (w == 0) {
        int s = wsum[lane];
        int sinc = s;
        #pragma unroll
        for (int o = 1; o < 32; o <<= 1) {
            int u = __shfl_up_sync(0xffffffffu, sinc, o);
            if (lane >= o) sinc += u;
        }
        wsum[lane] = sinc - s;
        if (lane == 31) g_rowptr[n] = sinc;
    }
    __syncthreads();
    if (t < nb) g_boff[t] = wsum[w] + inc - v;
}

__global__ void k_scan3(int n) {
    int i = blockIdx.x * blockDim.x + threadIdx.x;
    if (i < n) g_rowptr[i] += g_boff[i / SCB];
}

// -------- CSR fill --------
__global__ void k_fill(const int* __restrict__ ei, int E, int n) {
    int e = blockIdx.x * blockDim.x + threadIdx.x;
    if (e >= E) return;
    int s = ei[e];
    int d = ei[E + e];
    if ((unsigned)s >= (unsigned)n || (unsigned)d >= (unsigned)n) { s = 0; d = 0; }
    int pos = g_rowptr[d] + atomicAdd(&g_fill[d], 1);
    g_csrc[pos] = s;
}

// -------- graph boundaries (batch sorted, int32) --------
__global__ void k_bound(const int* __restrict__ batch, int n) {
    int i = blockIdx.x * blockDim.x + threadIdx.x;
    if (i >= n) return;
    int b = batch[i];
    if ((unsigned)b >= GNUM) return;
    atomicAdd(&g_icnt[b], 1);
    if (i == 0 || batch[i - 1] != b) atomicMin(&g_start[b], i);
}

// -------- register-blocked GEMM: thread-per-node, W broadcast from smem --------
// OUT[node, 0..MOUT) = X[node,:] @ W ; epilogue: bias+relu and/or *dinv
template<int K, int MOUT, bool BIASRELU, bool SCALE>
__global__ void k_gemmr(const float* __restrict__ X, const float* __restrict__ W,
                        const float* __restrict__ bias, float* __restrict__ OUT, int n) {
    constexpr int K4 = K / 4, M4 = MOUT / 4;
    __shared__ float4 Ws[K * M4];
    int tid = threadIdx.x;
    for (int i = tid; i < K * M4; i += blockDim.x)
        Ws[i] = ((const float4*)W)[i];
    __syncthreads();
    int node = blockIdx.x * blockDim.x + tid;
    if (node >= n) return;
    const float4* xr = (const float4*)(X + (size_t)node * K);
    float4 acc[M4];
    #pragma unroll
    for (int m = 0; m < M4; m++) acc[m] = make_float4(0.f, 0.f, 0.f, 0.f);
    #pragma unroll 4
    for (int k4 = 0; k4 < K4; k4++) {
        float4 x4 = __ldg(&xr[k4]);
        #pragma unroll
        for (int m = 0; m < M4; m++) {
            float4 w0 = Ws[(4 * k4 + 0) * M4 + m];
            float4 w1 = Ws[(4 * k4 + 1) * M4 + m];
            float4 w2 = Ws[(4 * k4 + 2) * M4 + m];
            float4 w3 = Ws[(4 * k4 + 3) * M4 + m];
            acc[m].x += x4.x * w0.x + x4.y * w1.x + x4.z * w2.x + x4.w * w3.x;
            acc[m].y += x4.x * w0.y + x4.y * w1.y + x4.z * w2.y + x4.w * w3.y;
            acc[m].z += x4.x * w0.z + x4.y * w1.z + x4.z * w2.z + x4.w * w3.z;
            acc[m].w += x4.x * w0.w + x4.y * w1.w + x4.z * w2.w + x4.w * w3.w;
        }
    }
    float sc = SCALE ? g_dinv[node] : 1.f;
    float4* orow = (float4*)(OUT + (size_t)node * MOUT);
    #pragma unroll
    for (int m = 0; m < M4; m++) {
        float4 a = acc[m];
        if (BIASRELU) {
            a.x = fmaxf(a.x + __ldg(&bias[4 * m + 0]), 0.f);
            a.y = fmaxf(a.y + __ldg(&bias[4 * m + 1]), 0.f);
            a.z = fmaxf(a.z + __ldg(&bias[4 * m + 2]), 0.f);
            a.w = fmaxf(a.w + __ldg(&bias[4 * m + 3]), 0.f);
        }
        if (SCALE) { a.x *= sc; a.y *= sc; a.z *= sc; a.w *= sc; }
        orow[m] = a;
    }
}

// -------- warp-per-node gather (unroll 2): dst_i = dinv_i*(Σ src_nbr + src_i) ----
template<int F4, bool RELU, bool HASB, bool SCALEOUT>  // F4 in {4,8}
__global__ void k_gatherw(const float4* __restrict__ src, float4* __restrict__ dst,
                          const float* __restrict__ bias, int n) {
    int wid = (blockIdx.x * blockDim.x + threadIdx.x) >> 5;
    if (wid >= n) return;
    const int EPW = 32 / F4;
    int lane = threadIdx.x & 31;
    int e_l = lane / F4;
    int g   = lane & (F4 - 1);
    int beg = g_rowptr[wid], end = g_rowptr[wid + 1];
    float4 a0 = make_float4(0.f, 0.f, 0.f, 0.f);
    float4 a1 = make_float4(0.f, 0.f, 0.f, 0.f);
    int j = beg + e_l;
    for (; j + EPW < end; j += 2 * EPW) {
        int s0 = __ldg(&g_csrc[j]);
        int s1 = __ldg(&g_csrc[j + EPW]);
        float4 v0 = __ldg(&src[(size_t)s0 * F4 + g]);
        float4 v1 = __ldg(&src[(size_t)s1 * F4 + g]);
        a0.x += v0.x; a0.y += v0.y; a0.z += v0.z; a0.w += v0.w;
        a1.x += v1.x; a1.y += v1.y; a1.z += v1.z; a1.w += v1.w;
    }
    if (j < end) {
        int s0 = __ldg(&g_csrc[j]);
        float4 v0 = __ldg(&src[(size_t)s0 * F4 + g]);
        a0.x += v0.x; a0.y += v0.y; a0.z += v0.z; a0.w += v0.w;
    }
    float4 acc = make_float4(a0.x + a1.x, a0.y + a1.y, a0.z + a1.z, a0.w + a1.w);
    #pragma unroll
    for (int off = 16; off >= F4; off >>= 1) {
        acc.x += __shfl_xor_sync(0xffffffffu, acc.x, off);
        acc.y += __shfl_xor_sync(0xffffffffu, acc.y, off);
        acc.z += __shfl_xor_sync(0xffffffffu, acc.z, off);
        acc.w += __shfl_xor_sync(0xffffffffu, acc.w, off);
    }
    if (lane < F4) {
        float di = g_dinv[wid];
        float4 hv = src[(size_t)wid * F4 + g];
        float rx = (acc.x + hv.x) * di;
        float ry = (acc.y + hv.y) * di;
        float rz = (acc.z + hv.z) * di;
        float rw = (acc.w + hv.w) * di;
        if (HASB) {
            rx += __ldg(&bias[4 * g + 0]); ry += __ldg(&bias[4 * g + 1]);
            rz += __ldg(&bias[4 * g + 2]); rw += __ldg(&bias[4 * g + 3]);
        }
        if (RELU) {
            rx = fmaxf(rx, 0.f); ry = fmaxf(ry, 0.f);
            rz = fmaxf(rz, 0.f); rw = fmaxf(rw, 0.f);
        }
        if (SCALEOUT) { rx *= di; ry *= di; rz *= di; rw *= di; }
        dst[(size_t)wid * F4 + g] = make_float4(rx, ry, rz, rw);
    }
}

// -------- mean pool (batch sorted => contiguous ranges) --------
__global__ void k_pool(const float* __restrict__ fsrc) {
    int g = blockIdx.x;
    int t = threadIdx.x;
    int f = t & 31, p = t >> 5;
    int cnt = g_icnt[g];
    int beg = g_start[g];
    float s = 0.f;
    for (int k = p; k < cnt; k += 8)
        s += fsrc[(size_t)(beg + k) * 32 + f];
    __shared__ float sh[256];
    sh[t] = s;
    __syncthreads();
    if (p == 0) {
        float tot = 0.f;
        #pragma unroll
        for (int q = 0; q < 8; q++) tot += sh[q * 32 + f];
        g_pool[g * 32 + f] = tot / fmaxf((float)cnt, 1.f);
    }
}

// -------- MLP head --------
__global__ void k_head(const float* __restrict__ Wa, const float* __restrict__ ba,
                       const float* __restrict__ Wo, const float* __restrict__ bo,
                       float* __restrict__ out) {
    __shared__ float a[64];
    __shared__ float ps[32];
    int g = blockIdx.x, t = threadIdx.x;
    if (t < 32) ps[t] = g_pool[g * 32 + t];
    __syncthreads();
    float acc = ba[t];
    #pragma unroll
    for (int k = 0; k < 32; k++) acc += ps[k] * Wa[k * 64 + t];
    a[t] = fmaxf(acc, 0.f);
    __syncthreads();
    if (t < 32) {
        float o = bo[t];
        #pragma unroll
        for (int k = 0; k < 64; k++) o += a[k] * Wo[k * 32 + t];
        out[g * 32 + t] = tanhf(o);
    }
}

// ============================================================================
extern "C" void kernel_launch(void* const* d_in, const int* in_sizes, int n_in,
                              void* d_out, int out_size) {
    const float* x     = (const float*)d_in[0];
    const int*   ei    = (const int*)d_in[1];
    const int*   batch = (const int*)d_in[2];
    const float* W1 = (const float*)d_in[3];  const float* b1 = (const float*)d_in[4];
    const float* W2 = (const float*)d_in[5];  const float* b2 = (const float*)d_in[6];
    const float* W3 = (const float*)d_in[7];  const float* b3 = (const float*)d_in[8];
    const float* Wa = (const float*)d_in[9];  const float* ba = (const float*)d_in[10];
    const float* Wo = (const float*)d_in[11]; const float* bo = (const float*)d_in[12];
    float* out = (float*)d_out;

    int N = in_sizes[0] / FIN;
    int E = in_sizes[1] / 2;
    if (N > NMAX) N = NMAX;
    if (E > EMAX) E = EMAX;
    int nb = (N + SCB - 1) / SCB;

    void *pA = nullptr, *pB = nullptr;
    cudaGetSymbolAddress(&pA, g_A);
    cudaGetSymbolAddress(&pB, g_B);
    float4* A4 = (float4*)pA;  float* Af = (float*)pA;
    float4* B4 = (float4*)pB;  float* Bf = (float*)pB;

    const int TB = 256;
    auto blocks = [](long long work, int tb) { return (int)((work + tb - 1) / tb); };
    int gw = blocks((long long)N * 32, TB);   // warp-per-node gather grid
    int gn = blocks(N, TB);                   // thread-per-node grid

    // ---- CSR build + dinv (shared by all 3 layers) ----
    k_init<<<gn, TB>>>(N);
    k_prep<<<blocks(E, TB), TB>>>(ei, E, N);
    k_dinv<<<gn, TB>>>(N);
    k_scan1<<<nb, SCB>>>(N);
    k_scan2<<<1, SCB>>>(nb, N);
    k_scan3<<<gn, TB>>>(N);
    k_fill<<<blocks(E, TB), TB>>>(ei, E, N);
    k_bound<<<gn, TB>>>(batch, N);

    // ---- layer 1: z1s = dinv*(x@W1); h1s = dinv*relu(dinv*(Σ z1s) + b1) ----
    k_gemmr<128, 16, false, true><<<gn, TB>>>(x, W1, nullptr, Af, N);
    k_gatherw<4, true, true, true><<<gw, TB>>>(A4, B4, b1, N);

    // ---- layer 2: agg2 = dinv*(Σ h1s); h2 = relu(agg2@W2 + b2) ----
    k_gatherw<4, false, false, false><<<gw, TB>>>(B4, A4, nullptr, N);
    k_gemmr<16, 64, true, false><<<gn, TB>>>(Af, W2, b2, Bf, N);

    // ---- layer 3: z3s = dinv*(h2@W3); h3 = dinv*(Σ z3s) + b3 ----
    k_gemmr<64, 32, false, true><<<gn, TB>>>(Bf, W3, nullptr, Af, N);
    k_gatherw<8, false, true, false><<<gw, TB>>>(A4, B4, b3, N);

    // ---- pool + head ----
    k_pool<<<GNUM, 256>>>(Bf);
    k_head<<<GNUM, 64>>>(Wa, ba, Wo, bo, out);
}

// round 8
// speedup vs baseline: 1.7339x; 1.0562x over previous
#include <cuda_runtime.h>
#include <cuda_bf16.h>
#include <math.h>

#define NMAX 100000
#define EMAX 3200000
#define GNUM 64
#define FIN  128
#define SCB  1024
#define NBLK ((NMAX + SCB - 1) / SCB)

// -------- device scratch --------
__device__ float4 g_A [(size_t)NMAX * 16];   // ping (max F=64)
__device__ float4 g_B [(size_t)NMAX * 16];   // pong
__device__ float  g_dinv[NMAX];
__device__ int    g_deg [NMAX];
__device__ int    g_fill[NMAX];              // seeded with rowptr by k_scan3
__device__ int    g_rowptr[NMAX + 1];
__device__ int    g_bsum[NBLK];
__device__ int    g_boff[NBLK];
__device__ int    g_csrc[EMAX];              // CSR (by dst): source node per slot
__device__ float  g_pool[GNUM * 32];

// -------- degree count on dst (2 edges per thread, int2 loads) --------
__global__ void k_prep(const int* __restrict__ ei, int E, int n) {
    int e2 = blockIdx.x * blockDim.x + threadIdx.x;
    int base = 2 * e2;
    if (base >= E) return;
    if (base + 1 < E) {
        int2 d2 = *(const int2*)(ei + E + base);   // dst array, 8B aligned
        int d0 = ((unsigned)d2.x < (unsigned)n) ? d2.x : 0;
        int d1 = ((unsigned)d2.y < (unsigned)n) ? d2.y : 0;
        atomicAdd(&g_deg[d0], 1);
        atomicAdd(&g_deg[d1], 1);
    } else {
        int d = ei[E + base];
        if ((unsigned)d >= (unsigned)n) d = 0;
        atomicAdd(&g_deg[d], 1);
    }
}

// -------- phase 1 scan (+ fused dinv) --------
__global__ void k_scan1(int n) {
    __shared__ int wsum[32];
    int t = threadIdx.x, lane = t & 31, w = t >> 5;
    int i = blockIdx.x * SCB + t;
    int v = (i < n) ? g_deg[i] : 0;
    if (i < n) g_dinv[i] = rsqrtf((float)v + 1.0f);
    int inc = v;
    #pragma unroll
    for (int o = 1; o < 32; o <<= 1) {
        int u = __shfl_up_sync(0xffffffffu, inc, o);
        if (lane >= o) inc += u;
    }
    if (lane == 31) wsum[w] = inc;
    __syncthreads();
    if (w == 0) {
        int s = wsum[lane];
        int sinc = s;
        #pragma unroll
        for (int o = 1; o < 32; o <<= 1) {
            int u = __shfl_up_sync(0xffffffffu, sinc, o);
            if (lane >= o) sinc += u;
        }
        wsum[lane] = sinc - s;
        if (lane == 31) g_bsum[blockIdx.x] = sinc;
    }
    __syncthreads();
    if (i < n) g_rowptr[i] = wsum[w] + inc - v;
}

__global__ void k_scan2(int nb, int n) {
    __shared__ int wsum[32];
    int t = threadIdx.x, lane = t & 31, w = t >> 5;
    int v = (t < nb) ? g_bsum[t] : 0;
    int inc = v;
    #pragma unroll
    for (int o = 1; o < 32; o <<= 1) {
        int u = __shfl_up_sync(0xffffffffu, inc, o);
        if (lane >= o) inc += u;
    }
    if (lane == 31) wsum[w] = inc;
    __syncthreads();
    if (w == 0) {
        int s = wsum[lane];
        int sinc = s;
        #pragma unroll
        for (int o = 1; o < 32; o <<= 1) {
            int u = __shfl_up_sync(0xffffffffu, sinc, o);
            if (lane >= o) sinc += u;
        }
        wsum[lane] = sinc - s;
        if (lane == 31) g_rowptr[n] = sinc;
    }
    __syncthreads();
    if (t < nb) g_boff[t] = wsum[w] + inc - v;
}

// -------- phase 3: add block offsets; seed g_fill with final rowptr --------
__global__ void k_scan3(int n) {
    int i = blockIdx.x * blockDim.x + threadIdx.x;
    if (i < n) {
        int r = g_rowptr[i] + g_boff[i / SCB];
        g_rowptr[i] = r;
        g_fill[i]   = r;
    }
}

// -------- CSR fill: cursor atomics only --------
__global__ void k_fill(const int* __restrict__ ei, int E, int n) {
    int e = blockIdx.x * blockDim.x + threadIdx.x;
    if (e >= E) return;
    int s = ei[e];
    int d = ei[E + e];
    if ((unsigned)s >= (unsigned)n || (unsigned)d >= (unsigned)n) { s = 0; d = 0; }
    int pos = atomicAdd(&g_fill[d], 1);
    g_csrc[pos] = s;
}

// -------- register-blocked GEMM: thread-per-node, W broadcast from smem --------
template<int K, int MOUT, bool BIASRELU, bool SCALE>
__global__ void k_gemmr(const float* __restrict__ X, const float* __restrict__ W,
                        const float* __restrict__ bias, float* __restrict__ OUT, int n) {
    constexpr int K4 = K / 4, M4 = MOUT / 4;
    __shared__ float4 Ws[K * M4];
    int tid = threadIdx.x;
    for (int i = tid; i < K * M4; i += blockDim.x)
        Ws[i] = ((const float4*)W)[i];
    __syncthreads();
    int node = blockIdx.x * blockDim.x + tid;
    if (node >= n) return;
    const float4* xr = (const float4*)(X + (size_t)node * K);
    float4 acc[M4];
    #pragma unroll
    for (int m = 0; m < M4; m++) acc[m] = make_float4(0.f, 0.f, 0.f, 0.f);
    #pragma unroll 4
    for (int k4 = 0; k4 < K4; k4++) {
        float4 x4 = __ldg(&xr[k4]);
        #pragma unroll
        for (int m = 0; m < M4; m++) {
            float4 w0 = Ws[(4 * k4 + 0) * M4 + m];
            float4 w1 = Ws[(4 * k4 + 1) * M4 + m];
            float4 w2 = Ws[(4 * k4 + 2) * M4 + m];
            float4 w3 = Ws[(4 * k4 + 3) * M4 + m];
            acc[m].x += x4.x * w0.x + x4.y * w1.x + x4.z * w2.x + x4.w * w3.x;
            acc[m].y += x4.x * w0.y + x4.y * w1.y + x4.z * w2.y + x4.w * w3.y;
            acc[m].z += x4.x * w0.z + x4.y * w1.z + x4.z * w2.z + x4.w * w3.z;
            acc[m].w += x4.x * w0.w + x4.y * w1.w + x4.z * w2.w + x4.w * w3.w;
        }
    }
    float sc = SCALE ? g_dinv[node] : 1.f;
    float4* orow = (float4*)(OUT + (size_t)node * MOUT);
    #pragma unroll
    for (int m = 0; m < M4; m++) {
        float4 a = acc[m];
        if (BIASRELU) {
            a.x = fmaxf(a.x + __ldg(&bias[4 * m + 0]), 0.f);
            a.y = fmaxf(a.y + __ldg(&bias[4 * m + 1]), 0.f);
            a.z = fmaxf(a.z + __ldg(&bias[4 * m + 2]), 0.f);
            a.w = fmaxf(a.w + __ldg(&bias[4 * m + 3]), 0.f);
        }
        if (SCALE) { a.x *= sc; a.y *= sc; a.z *= sc; a.w *= sc; }
        orow[m] = a;
    }
}

// -------- warp-per-node gather (unroll 4): dst_i = dinv_i*(Σ src_nbr + src_i) ----
template<int F4, bool RELU, bool HASB, bool SCALEOUT>  // F4 in {4,8}
__global__ void k_gatherw(const float4* __restrict__ src, float4* __restrict__ dst,
                          const float* __restrict__ bias, int n) {
    int wid = (blockIdx.x * blockDim.x + threadIdx.x) >> 5;
    if (wid >= n) return;
    const int EPW = 32 / F4;
    int lane = threadIdx.x & 31;
    int e_l = lane / F4;
    int g   = lane & (F4 - 1);
    int beg = g_rowptr[wid], end = g_rowptr[wid + 1];
    float4 a0 = make_float4(0.f, 0.f, 0.f, 0.f);
    float4 a1 = make_float4(0.f, 0.f, 0.f, 0.f);
    float4 a2 = make_float4(0.f, 0.f, 0.f, 0.f);
    float4 a3 = make_float4(0.f, 0.f, 0.f, 0.f);
    int j = beg + e_l;
    for (; j + 3 * EPW < end; j += 4 * EPW) {
        int s0 = __ldg(&g_csrc[j]);
        int s1 = __ldg(&g_csrc[j + EPW]);
        int s2 = __ldg(&g_csrc[j + 2 * EPW]);
        int s3 = __ldg(&g_csrc[j + 3 * EPW]);
        float4 v0 = __ldg(&src[(size_t)s0 * F4 + g]);
        float4 v1 = __ldg(&src[(size_t)s1 * F4 + g]);
        float4 v2 = __ldg(&src[(size_t)s2 * F4 + g]);
        float4 v3 = __ldg(&src[(size_t)s3 * F4 + g]);
        a0.x += v0.x; a0.y += v0.y; a0.z += v0.z; a0.w += v0.w;
        a1.x += v1.x; a1.y += v1.y; a1.z += v1.z; a1.w += v1.w;
        a2.x += v2.x; a2.y += v2.y; a2.z += v2.z; a2.w += v2.w;
        a3.x += v3.x; a3.y += v3.y; a3.z += v3.z; a3.w += v3.w;
    }
    for (; j < end; j += EPW) {
        int s0 = __ldg(&g_csrc[j]);
        float4 v0 = __ldg(&src[(size_t)s0 * F4 + g]);
        a0.x += v0.x; a0.y += v0.y; a0.z += v0.z; a0.w += v0.w;
    }
    float4 acc = make_float4(a0.x + a1.x + a2.x + a3.x,
                             a0.y + a1.y + a2.y + a3.y,
                             a0.z + a1.z + a2.z + a3.z,
                             a0.w + a1.w + a2.w + a3.w);
    #pragma unroll
    for (int off = 16; off >= F4; off >>= 1) {
        acc.x += __shfl_xor_sync(0xffffffffu, acc.x, off);
        acc.y += __shfl_xor_sync(0xffffffffu, acc.y, off);
        acc.z += __shfl_xor_sync(0xffffffffu, acc.z, off);
        acc.w += __shfl_xor_sync(0xffffffffu, acc.w, off);
    }
    if (lane < F4) {
        float di = g_dinv[wid];
        float4 hv = src[(size_t)wid * F4 + g];
        float rx = (acc.x + hv.x) * di;
        float ry = (acc.y + hv.y) * di;
        float rz = (acc.z + hv.z) * di;
        float rw = (acc.w + hv.w) * di;
        if (HASB) {
            rx += __ldg(&bias[4 * g + 0]); ry += __ldg(&bias[4 * g + 1]);
            rz += __ldg(&bias[4 * g + 2]); rw += __ldg(&bias[4 * g + 3]);
        }
        if (RELU) {
            rx = fmaxf(rx, 0.f); ry = fmaxf(ry, 0.f);
            rz = fmaxf(rz, 0.f); rw = fmaxf(rw, 0.f);
        }
        if (SCALEOUT) { rx *= di; ry *= di; rz *= di; rw *= di; }
        dst[(size_t)wid * F4 + g] = make_float4(rx, ry, rz, rw);
    }
}

// -------- mean pool: boundaries via binary search on sorted batch --------
__global__ void k_pool(const float* __restrict__ fsrc, const int* __restrict__ batch, int n) {
    __shared__ int bounds[2];
    int g = blockIdx.x;
    int t = threadIdx.x;
    if (t == 0) {
        // lower_bound(batch, g) and lower_bound(batch, g+1)
        int lo = 0, hi = n;
        while (lo < hi) { int mid = (lo + hi) >> 1; if (batch[mid] < g) lo = mid + 1; else hi = mid; }
        bounds[0] = lo;
        hi = n; // lo continues from previous (batch sorted, g+1 >= g)
        int lo2 = lo;
        while (lo2 < hi) { int mid = (lo2 + hi) >> 1; if (batch[mid] < g + 1) lo2 = mid + 1; else hi = mid; }
        bounds[1] = lo2;
    }
    __syncthreads();
    int beg = bounds[0], cnt = bounds[1] - bounds[0];
    int f = t & 31, p = t >> 5;   // 8 partials per feature
    float s = 0.f;
    for (int k = p; k < cnt; k += 8)
        s += fsrc[(size_t)(beg + k) * 32 + f];
    __shared__ float sh[256];
    sh[t] = s;
    __syncthreads();
    if (p == 0) {
        float tot = 0.f;
        #pragma unroll
        for (int q = 0; q < 8; q++) tot += sh[q * 32 + f];
        g_pool[g * 32 + f] = tot / fmaxf((float)cnt, 1.f);
    }
}

// -------- MLP head --------
__global__ void k_head(const float* __restrict__ Wa, const float* __restrict__ ba,
                       const float* __restrict__ Wo, const float* __restrict__ bo,
                       float* __restrict__ out) {
    __shared__ float a[64];
    __shared__ float ps[32];
    int g = blockIdx.x, t = threadIdx.x;
    if (t < 32) ps[t] = g_pool[g * 32 + t];
    __syncthreads();
    float acc = ba[t];
    #pragma unroll
    for (int k = 0; k < 32; k++) acc += ps[k] * Wa[k * 64 + t];
    a[t] = fmaxf(acc, 0.f);
    __syncthreads();
    if (t < 32) {
        float o = bo[t];
        #pragma unroll
        for (int k = 0; k < 64; k++) o += a[k] * Wo[k * 32 + t];
        out[g * 32 + t] = tanhf(o);
    }
}

// ============================================================================
extern "C" void kernel_launch(void* const* d_in, const int* in_sizes, int n_in,
                              void* d_out, int out_size) {
    const float* x     = (const float*)d_in[0];
    const int*   ei    = (const int*)d_in[1];
    const int*   batch = (const int*)d_in[2];
    const float* W1 = (const float*)d_in[3];  const float* b1 = (const float*)d_in[4];
    const float* W2 = (const float*)d_in[5];  const float* b2 = (const float*)d_in[6];
    const float* W3 = (const float*)d_in[7];  const float* b3 = (const float*)d_in[8];
    const float* Wa = (const float*)d_in[9];  const float* ba = (const float*)d_in[10];
    const float* Wo = (const float*)d_in[11]; const float* bo = (const float*)d_in[12];
    float* out = (float*)d_out;

    int N = in_sizes[0] / FIN;
    int E = in_sizes[1] / 2;
    if (N > NMAX) N = NMAX;
    if (E > EMAX) E = EMAX;
    int nb = (N + SCB - 1) / SCB;

    void *pA = nullptr, *pB = nullptr, *pDeg = nullptr;
    cudaGetSymbolAddress(&pA, g_A);
    cudaGetSymbolAddress(&pB, g_B);
    cudaGetSymbolAddress(&pDeg, g_deg);
    float4* A4 = (float4*)pA;  float* Af = (float*)pA;
    float4* B4 = (float4*)pB;  float* Bf = (float*)pB;

    const int TB = 256;
    auto blocks = [](long long work, int tb) { return (int)((work + tb - 1) / tb); };
    int gw = blocks((long long)N * 32, TB);   // warp-per-node gather grid
    int gn = blocks(N, TB);                   // thread-per-node grid

    // ---- CSR build + dinv (shared by all 3 layers) ----
    cudaMemsetAsync(pDeg, 0, (size_t)N * sizeof(int));
    k_prep<<<blocks((E + 1) / 2, TB), TB>>>(ei, E, N);
    k_scan1<<<nb, SCB>>>(N);
    k_scan2<<<1, SCB>>>(nb, N);
    k_scan3<<<gn, TB>>>(N);
    k_fill<<<blocks(E, TB), TB>>>(ei, E, N);

    // ---- layer 1: z1s = dinv*(x@W1); h1s = dinv*relu(dinv*(Σ z1s) + b1) ----
    k_gemmr<128, 16, false, true><<<gn, TB>>>(x, W1, nullptr, Af, N);
    k_gatherw<4, true, true, true><<<gw, TB>>>(A4, B4, b1, N);

    // ---- layer 2: agg2 = dinv*(Σ h1s); h2 = relu(agg2@W2 + b2) ----
    k_gatherw<4, false, false, false><<<gw, TB>>>(B4, A4, nullptr, N);
    k_gemmr<16, 64, true, false><<<gn, TB>>>(Af, W2, b2, Bf, N);

    // ---- layer 3: z3s = dinv*(h2@W3); h3 = dinv*(Σ z3s) + b3 ----
    k_gemmr<64, 32, false, true><<<gn, TB>>>(Bf, W3, nullptr, Af, N);
    k_gatherw<8, false, true, false><<<gw, TB>>>(A4, B4, b3, N);

    // ---- pool + head ----
    k_pool<<<GNUM, 256>>>(Bf, batch, N);
    k_head<<<GNUM, 64>>>(Wa, ba, Wo, bo, out);
}

// round 9
// speedup vs baseline: 1.7937x; 1.0345x over previous
#include <cuda_runtime.h>
#include <cuda_fp16.h>
#include <math.h>

#define NMAX 100000
#define EMAX 3200000
#define GNUM 64
#define FIN  128
#define SCB  1024
#define NBLK ((NMAX + SCB - 1) / SCB)

// -------- device scratch: half feature buffers (uint4 => 16B aligned) --------
__device__ uint4  g_A[(size_t)NMAX * 8];     // N x (<=64) halfs, ping
__device__ uint4  g_B[(size_t)NMAX * 8];     // pong
__device__ float  g_dinv[NMAX];
__device__ int    g_deg [NMAX];
__device__ int    g_fill[NMAX];              // seeded with rowptr by k_scan3
__device__ int    g_rowptr[NMAX + 1];
__device__ int    g_bsum[NBLK];
__device__ int    g_boff[NBLK];
__device__ int    g_csrc[EMAX];
__device__ float  g_pool[GNUM * 32];

// -------- half pack/unpack helpers --------
__device__ __forceinline__ float2 uph(unsigned v) {
    __half2 h = *reinterpret_cast<__half2*>(&v);
    return __half22float2(h);
}
__device__ __forceinline__ unsigned pack2(float x, float y) {
    __half2 h = __floats2half2_rn(x, y);
    return *reinterpret_cast<unsigned*>(&h);
}
__device__ __forceinline__ uint2 pack4(float4 a) {
    return make_uint2(pack2(a.x, a.y), pack2(a.z, a.w));
}
__device__ __forceinline__ void acc8(float* a, uint4 u) {
    float2 f0 = uph(u.x), f1 = uph(u.y), f2 = uph(u.z), f3 = uph(u.w);
    a[0] += f0.x; a[1] += f0.y; a[2] += f1.x; a[3] += f1.y;
    a[4] += f2.x; a[5] += f2.y; a[6] += f3.x; a[7] += f3.y;
}

// -------- degree count on dst (2 edges per thread) --------
__global__ void k_prep(const int* __restrict__ ei, int E, int n) {
    int base = 2 * (blockIdx.x * blockDim.x + threadIdx.x);
    if (base >= E) return;
    if (base + 1 < E) {
        int2 d2 = *(const int2*)(ei + E + base);
        int d0 = ((unsigned)d2.x < (unsigned)n) ? d2.x : 0;
        int d1 = ((unsigned)d2.y < (unsigned)n) ? d2.y : 0;
        atomicAdd(&g_deg[d0], 1);
        atomicAdd(&g_deg[d1], 1);
    } else {
        int d = ei[E + base];
        if ((unsigned)d >= (unsigned)n) d = 0;
        atomicAdd(&g_deg[d], 1);
    }
}

// -------- 3-phase scan (+ fused dinv) --------
__global__ void k_scan1(int n) {
    __shared__ int wsum[32];
    int t = threadIdx.x, lane = t & 31, w = t >> 5;
    int i = blockIdx.x * SCB + t;
    int v = (i < n) ? g_deg[i] : 0;
    if (i < n) g_dinv[i] = rsqrtf((float)v + 1.0f);
    int inc = v;
    #pragma unroll
    for (int o = 1; o < 32; o <<= 1) {
        int u = __shfl_up_sync(0xffffffffu, inc, o);
        if (lane >= o) inc += u;
    }
    if (lane == 31) wsum[w] = inc;
    __syncthreads();
    if (w == 0) {
        int s = wsum[lane];
        int sinc = s;
        #pragma unroll
        for (int o = 1; o < 32; o <<= 1) {
            int u = __shfl_up_sync(0xffffffffu, sinc, o);
            if (lane >= o) sinc += u;
        }
        wsum[lane] = sinc - s;
        if (lane == 31) g_bsum[blockIdx.x] = sinc;
    }
    __syncthreads();
    if (i < n) g_rowptr[i] = wsum[w] + inc - v;
}

__global__ void k_scan2(int nb, int n) {
    __shared__ int wsum[32];
    int t = threadIdx.x, lane = t & 31, w = t >> 5;
    int v = (t < nb) ? g_bsum[t] : 0;
    int inc = v;
    #pragma unroll
    for (int o = 1; o < 32; o <<= 1) {
        int u = __shfl_up_sync(0xffffffffu, inc, o);
        if (lane >= o) inc += u;
    }
    if (lane == 31) wsum[w] = inc;
    __syncthreads();
    if (w == 0) {
        int s = wsum[lane];
        int sinc = s;
        #pragma unroll
        for (int o = 1; o < 32; o <<= 1) {
            int u = __shfl_up_sync(0xffffffffu, sinc, o);
            if (lane >= o) sinc += u;
        }
        wsum[lane] = sinc - s;
        if (lane == 31) g_rowptr[n] = sinc;
    }
    __syncthreads();
    if (t < nb) g_boff[t] = wsum[w] + inc - v;
}

__global__ void k_scan3(int n) {
    int i = blockIdx.x * blockDim.x + threadIdx.x;
    if (i < n) {
        int r = g_rowptr[i] + g_boff[i / SCB];
        g_rowptr[i] = r;
        g_fill[i]   = r;
    }
}

// -------- CSR fill: cursor atomics --------
__global__ void k_fill(const int* __restrict__ ei, int E, int n) {
    int e = blockIdx.x * blockDim.x + threadIdx.x;
    if (e >= E) return;
    int s = ei[e];
    int d = ei[E + e];
    if ((unsigned)s >= (unsigned)n || (unsigned)d >= (unsigned)n) { s = 0; d = 0; }
    int pos = atomicAdd(&g_fill[d], 1);
    g_csrc[pos] = s;
}

// -------- GEMM, fp32 input (layer 1: K=128), half output --------
template<int K, int MOUT, bool BIASRELU, bool SCALE>
__global__ void k_gemmf(const float* __restrict__ X, const float* __restrict__ W,
                        const float* __restrict__ bias, uint2* __restrict__ OUT, int n) {
    constexpr int K4 = K / 4, M4 = MOUT / 4;
    __shared__ float4 Ws[K * M4];
    int tid = threadIdx.x;
    for (int i = tid; i < K * M4; i += blockDim.x)
        Ws[i] = ((const float4*)W)[i];
    __syncthreads();
    int node = blockIdx.x * blockDim.x + tid;
    if (node >= n) return;
    const float4* xr = (const float4*)(X + (size_t)node * K);
    float4 acc[M4];
    #pragma unroll
    for (int m = 0; m < M4; m++) acc[m] = make_float4(0.f, 0.f, 0.f, 0.f);
    #pragma unroll 4
    for (int k4 = 0; k4 < K4; k4++) {
        float4 x4 = __ldg(&xr[k4]);
        #pragma unroll
        for (int m = 0; m < M4; m++) {
            float4 w0 = Ws[(4 * k4 + 0) * M4 + m];
            float4 w1 = Ws[(4 * k4 + 1) * M4 + m];
            float4 w2 = Ws[(4 * k4 + 2) * M4 + m];
            float4 w3 = Ws[(4 * k4 + 3) * M4 + m];
            acc[m].x += x4.x * w0.x + x4.y * w1.x + x4.z * w2.x + x4.w * w3.x;
            acc[m].y += x4.x * w0.y + x4.y * w1.y + x4.z * w2.y + x4.w * w3.y;
            acc[m].z += x4.x * w0.z + x4.y * w1.z + x4.z * w2.z + x4.w * w3.z;
            acc[m].w += x4.x * w0.w + x4.y * w1.w + x4.z * w2.w + x4.w * w3.w;
        }
    }
    float sc = SCALE ? g_dinv[node] : 1.f;
    uint2* orow = OUT + (size_t)node * M4;
    #pragma unroll
    for (int m = 0; m < M4; m++) {
        float4 a = acc[m];
        if (BIASRELU) {
            a.x = fmaxf(a.x + __ldg(&bias[4 * m + 0]), 0.f);
            a.y = fmaxf(a.y + __ldg(&bias[4 * m + 1]), 0.f);
            a.z = fmaxf(a.z + __ldg(&bias[4 * m + 2]), 0.f);
            a.w = fmaxf(a.w + __ldg(&bias[4 * m + 3]), 0.f);
        }
        if (SCALE) { a.x *= sc; a.y *= sc; a.z *= sc; a.w *= sc; }
        orow[m] = pack4(a);
    }
}

// -------- GEMM, half input, half output --------
template<int K, int MOUT, bool BIASRELU, bool SCALE>
__global__ void k_gemmh(const uint4* __restrict__ X, const float* __restrict__ W,
                        const float* __restrict__ bias, uint2* __restrict__ OUT, int n) {
    constexpr int C = K / 8, M4 = MOUT / 4;
    __shared__ float4 Ws[K * M4];
    int tid = threadIdx.x;
    for (int i = tid; i < K * M4; i += blockDim.x)
        Ws[i] = ((const float4*)W)[i];
    __syncthreads();
    int node = blockIdx.x * blockDim.x + tid;
    if (node >= n) return;
    const uint4* xr = X + (size_t)node * C;
    float4 acc[M4];
    #pragma unroll
    for (int m = 0; m < M4; m++) acc[m] = make_float4(0.f, 0.f, 0.f, 0.f);
    #pragma unroll
    for (int c = 0; c < C; c++) {
        uint4 u = __ldg(&xr[c]);
        float xk[8];
        float2 f0 = uph(u.x), f1 = uph(u.y), f2 = uph(u.z), f3 = uph(u.w);
        xk[0] = f0.x; xk[1] = f0.y; xk[2] = f1.x; xk[3] = f1.y;
        xk[4] = f2.x; xk[5] = f2.y; xk[6] = f3.x; xk[7] = f3.y;
        #pragma unroll
        for (int kk = 0; kk < 8; kk++) {
            float xv = xk[kk];
            #pragma unroll
            for (int m = 0; m < M4; m++) {
                float4 w = Ws[(8 * c + kk) * M4 + m];
                acc[m].x += xv * w.x; acc[m].y += xv * w.y;
                acc[m].z += xv * w.z; acc[m].w += xv * w.w;
            }
        }
    }
    float sc = SCALE ? g_dinv[node] : 1.f;
    uint2* orow = OUT + (size_t)node * M4;
    #pragma unroll
    for (int m = 0; m < M4; m++) {
        float4 a = acc[m];
        if (BIASRELU) {
            a.x = fmaxf(a.x + __ldg(&bias[4 * m + 0]), 0.f);
            a.y = fmaxf(a.y + __ldg(&bias[4 * m + 1]), 0.f);
            a.z = fmaxf(a.z + __ldg(&bias[4 * m + 2]), 0.f);
            a.w = fmaxf(a.w + __ldg(&bias[4 * m + 3]), 0.f);
        }
        if (SCALE) { a.x *= sc; a.y *= sc; a.z *= sc; a.w *= sc; }
        orow[m] = pack4(a);
    }
}

// -------- warp-per-node half gather: dst_i = dinv_i*(Σ src_nbr + src_i) --------
// F halfs per row; LPR = F/8 uint4-lanes per row; EPW = 32/LPR edges per iter.
template<int F, bool RELU, bool HASB, bool SCALEOUT>
__global__ void k_gatherh(const uint4* __restrict__ src, uint4* __restrict__ dst,
                          const float* __restrict__ bias, int n) {
    constexpr int LPR = F / 8;
    constexpr int EPW = 32 / LPR;
    int wid = (blockIdx.x * blockDim.x + threadIdx.x) >> 5;
    if (wid >= n) return;
    int lane = threadIdx.x & 31;
    int e_l = lane / LPR;
    int g   = lane % LPR;
    int beg = g_rowptr[wid], end = g_rowptr[wid + 1];
    float a0[8] = {0,0,0,0,0,0,0,0};
    float a1[8] = {0,0,0,0,0,0,0,0};
    int j = beg + e_l;
    for (; j + EPW < end; j += 2 * EPW) {
        int s0 = __ldg(&g_csrc[j]);
        int s1 = __ldg(&g_csrc[j + EPW]);
        uint4 u0 = __ldg(&src[(size_t)s0 * LPR + g]);
        uint4 u1 = __ldg(&src[(size_t)s1 * LPR + g]);
        acc8(a0, u0);
        acc8(a1, u1);
    }
    if (j < end) {
        int s0 = __ldg(&g_csrc[j]);
        uint4 u0 = __ldg(&src[(size_t)s0 * LPR + g]);
        acc8(a0, u0);
    }
    #pragma unroll
    for (int q = 0; q < 8; q++) a0[q] += a1[q];
    #pragma unroll
    for (int off = 16; off >= LPR; off >>= 1) {
        #pragma unroll
        for (int q = 0; q < 8; q++)
            a0[q] += __shfl_xor_sync(0xffffffffu, a0[q], off);
    }
    if (lane < LPR) {
        uint4 hv = src[(size_t)wid * LPR + g];
        acc8(a0, hv);
        float di = g_dinv[wid];
        #pragma unroll
        for (int q = 0; q < 8; q++) a0[q] *= di;
        if (HASB) {
            #pragma unroll
            for (int q = 0; q < 8; q++) a0[q] += __ldg(&bias[8 * g + q]);
        }
        if (RELU) {
            #pragma unroll
            for (int q = 0; q < 8; q++) a0[q] = fmaxf(a0[q], 0.f);
        }
        if (SCALEOUT) {
            #pragma unroll
            for (int q = 0; q < 8; q++) a0[q] *= di;
        }
        uint4 o;
        o.x = pack2(a0[0], a0[1]); o.y = pack2(a0[2], a0[3]);
        o.z = pack2(a0[4], a0[5]); o.w = pack2(a0[6], a0[7]);
        dst[(size_t)wid * LPR + g] = o;
    }
}

// -------- mean pool (half input, boundaries via binary search) --------
__global__ void k_pool(const __half* __restrict__ fsrc, const int* __restrict__ batch, int n) {
    __shared__ int bounds[2];
    int g = blockIdx.x;
    int t = threadIdx.x;
    if (t == 0) {
        int lo = 0, hi = n;
        while (lo < hi) { int mid = (lo + hi) >> 1; if (batch[mid] < g) lo = mid + 1; else hi = mid; }
        bounds[0] = lo;
        int lo2 = lo; hi = n;
        while (lo2 < hi) { int mid = (lo2 + hi) >> 1; if (batch[mid] < g + 1) lo2 = mid + 1; else hi = mid; }
        bounds[1] = lo2;
    }
    __syncthreads();
    int beg = bounds[0], cnt = bounds[1] - bounds[0];
    int f = t & 31, p = t >> 5;
    float s = 0.f;
    for (int k = p; k < cnt; k += 8)
        s += __half2float(fsrc[(size_t)(beg + k) * 32 + f]);
    __shared__ float sh[256];
    sh[t] = s;
    __syncthreads();
    if (p == 0) {
        float tot = 0.f;
        #pragma unroll
        for (int q = 0; q < 8; q++) tot += sh[q * 32 + f];
        g_pool[g * 32 + f] = tot / fmaxf((float)cnt, 1.f);
    }
}

// -------- MLP head --------
__global__ void k_head(const float* __restrict__ Wa, const float* __restrict__ ba,
                       const float* __restrict__ Wo, const float* __restrict__ bo,
                       float* __restrict__ out) {
    __shared__ float a[64];
    __shared__ float ps[32];
    int g = blockIdx.x, t = threadIdx.x;
    if (t < 32) ps[t] = g_pool[g * 32 + t];
    __syncthreads();
    float acc = ba[t];
    #pragma unroll
    for (int k = 0; k < 32; k++) acc += ps[k] * Wa[k * 64 + t];
    a[t] = fmaxf(acc, 0.f);
    __syncthreads();
    if (t < 32) {
        float o = bo[t];
        #pragma unroll
        for (int k = 0; k < 64; k++) o += a[k] * Wo[k * 32 + t];
        out[g * 32 + t] = tanhf(o);
    }
}

// ============================================================================
extern "C" void kernel_launch(void* const* d_in, const int* in_sizes, int n_in,
                              void* d_out, int out_size) {
    const float* x     = (const float*)d_in[0];
    const int*   ei    = (const int*)d_in[1];
    const int*   batch = (const int*)d_in[2];
    const float* W1 = (const float*)d_in[3];  const float* b1 = (const float*)d_in[4];
    const float* W2 = (const float*)d_in[5];  const float* b2 = (const float*)d_in[6];
    const float* W3 = (const float*)d_in[7];  const float* b3 = (const float*)d_in[8];
    const float* Wa = (const float*)d_in[9];  const float* ba = (const float*)d_in[10];
    const float* Wo = (const float*)d_in[11]; const float* bo = (const float*)d_in[12];
    float* out = (float*)d_out;

    int N = in_sizes[0] / FIN;
    int E = in_sizes[1] / 2;
    if (N > NMAX) N = NMAX;
    if (E > EMAX) E = EMAX;
    int nb = (N + SCB - 1) / SCB;

    void *pA = nullptr, *pB = nullptr, *pDeg = nullptr;
    cudaGetSymbolAddress(&pA, g_A);
    cudaGetSymbolAddress(&pB, g_B);
    cudaGetSymbolAddress(&pDeg, g_deg);
    uint4* A4 = (uint4*)pA;  uint2* A2 = (uint2*)pA;
    uint4* B4 = (uint4*)pB;  uint2* B2 = (uint2*)pB;

    const int TB = 256;
    auto blocks = [](long long work, int tb) { return (int)((work + tb - 1) / tb); };
    int gw = blocks((long long)N * 32, TB);
    int gn = blocks(N, TB);

    // ---- CSR build + dinv ----
    cudaMemsetAsync(pDeg, 0, (size_t)N * sizeof(int));
    k_prep<<<blocks((E + 1) / 2, TB), TB>>>(ei, E, N);
    k_scan1<<<nb, SCB>>>(N);
    k_scan2<<<1, SCB>>>(nb, N);
    k_scan3<<<gn, TB>>>(N);
    k_fill<<<blocks(E, TB), TB>>>(ei, E, N);

    // ---- layer 1: z1s = dinv*(x@W1); h1s = dinv*relu(dinv*(Σ z1s) + b1) ----
    k_gemmf<128, 16, false, true><<<gn, TB>>>(x, W1, nullptr, A2, N);
    k_gatherh<16, true, true, true><<<gw, TB>>>(A4, B4, b1, N);

    // ---- layer 2: agg2 = dinv*(Σ h1s); h2 = relu(agg2@W2 + b2) ----
    k_gatherh<16, false, false, false><<<gw, TB>>>(B4, A4, nullptr, N);
    k_gemmh<16, 64, true, false><<<gn, TB>>>(A4, W2, b2, B2, N);

    // ---- layer 3: z3s = dinv*(h2@W3); h3 = dinv*(Σ z3s) + b3 ----
    k_gemmh<64, 32, false, true><<<gn, TB>>>(B4, W3, nullptr, A2, N);
    k_gatherh<32, false, true, false><<<gw, TB>>>(A4, B4, b3, N);

    // ---- pool + head ----
    k_pool<<<GNUM, 256>>>((const __half*)pB, batch, N);
    k_head<<<GNUM, 64>>>(Wa, ba, Wo, bo, out);
}

// round 10
// speedup vs baseline: 2.0539x; 1.1451x over previous
#include <cuda_runtime.h>
#include <cuda_fp16.h>
#include <math.h>

#define NMAX 100000
#define EMAX 3200000
#define GNUM 64
#define FIN  128
#define SCB  1024
#define NBLK ((NMAX + SCB - 1) / SCB)

// -------- device scratch --------
__device__ uint4  g_A[(size_t)NMAX * 8];     // N x (<=64) halfs, ping
__device__ uint4  g_B[(size_t)NMAX * 8];     // pong
__device__ float  g_dinv[NMAX];
__device__ int    g_deg [NMAX];
__device__ int    g_fill[NMAX];              // seeded with rowptr by k_scan3
__device__ int    g_rowptr[NMAX + 1];
__device__ int    g_bsum[NBLK];
__device__ int    g_boff[NBLK];
__device__ int    g_done;                    // scan1 completion counter
__device__ int    g_csrc[EMAX];

// -------- half helpers --------
__device__ __forceinline__ float2 uph(unsigned v) {
    __half2 h = *reinterpret_cast<__half2*>(&v);
    return __half22float2(h);
}
__device__ __forceinline__ unsigned pack2(float x, float y) {
    __half2 h = __floats2half2_rn(x, y);
    return *reinterpret_cast<unsigned*>(&h);
}
__device__ __forceinline__ uint2 pack4(float4 a) {
    return make_uint2(pack2(a.x, a.y), pack2(a.z, a.w));
}
__device__ __forceinline__ void acc8(float* a, uint4 u) {
    float2 f0 = uph(u.x), f1 = uph(u.y), f2 = uph(u.z), f3 = uph(u.w);
    a[0] += f0.x; a[1] += f0.y; a[2] += f1.x; a[3] += f1.y;
    a[4] += f2.x; a[5] += f2.y; a[6] += f3.x; a[7] += f3.y;
}

// -------- degree count on dst (2 edges per thread) --------
__global__ void k_prep(const int* __restrict__ ei, int E, int n) {
    int base = 2 * (blockIdx.x * blockDim.x + threadIdx.x);
    if (base >= E) return;
    if (base + 1 < E) {
        int2 d2 = *(const int2*)(ei + E + base);
        int d0 = ((unsigned)d2.x < (unsigned)n) ? d2.x : 0;
        int d1 = ((unsigned)d2.y < (unsigned)n) ? d2.y : 0;
        atomicAdd(&g_deg[d0], 1);
        atomicAdd(&g_deg[d1], 1);
    } else {
        int d = ei[E + base];
        if ((unsigned)d >= (unsigned)n) d = 0;
        atomicAdd(&g_deg[d], 1);
    }
}

// -------- scan phase 1 (+dinv) with fused phase-2 in last-arriving block --------
__global__ void k_scan1(int n, int nb) {
    __shared__ int wsum[32];
    __shared__ bool lastblk;
    int t = threadIdx.x, lane = t & 31, w = t >> 5;
    int i = blockIdx.x * SCB + t;
    int v = (i < n) ? g_deg[i] : 0;
    if (i < n) g_dinv[i] = rsqrtf((float)v + 1.0f);
    int inc = v;
    #pragma unroll
    for (int o = 1; o < 32; o <<= 1) {
        int u = __shfl_up_sync(0xffffffffu, inc, o);
        if (lane >= o) inc += u;
    }
    if (lane == 31) wsum[w] = inc;
    __syncthreads();
    if (w == 0) {
        int s = wsum[lane];
        int sinc = s;
        #pragma unroll
        for (int o = 1; o < 32; o <<= 1) {
            int u = __shfl_up_sync(0xffffffffu, sinc, o);
            if (lane >= o) sinc += u;
        }
        wsum[lane] = sinc - s;
        if (lane == 31) g_bsum[blockIdx.x] = sinc;
    }
    __syncthreads();
    if (i < n) g_rowptr[i] = wsum[w] + inc - v;

    // ---- last block performs the block-sum scan (phase 2) ----
    __threadfence();
    if (t == 0) lastblk = (atomicAdd(&g_done, 1) == nb - 1);
    __syncthreads();
    if (!lastblk) return;
    int v2 = (t < nb) ? g_bsum[t] : 0;
    int inc2 = v2;
    #pragma unroll
    for (int o = 1; o < 32; o <<= 1) {
        int u = __shfl_up_sync(0xffffffffu, inc2, o);
        if (lane >= o) inc2 += u;
    }
    __syncthreads();               // reuse wsum safely
    if (lane == 31) wsum[w] = inc2;
    __syncthreads();
    if (w == 0) {
        int s = wsum[lane];
        int sinc = s;
        #pragma unroll
        for (int o = 1; o < 32; o <<= 1) {
            int u = __shfl_up_sync(0xffffffffu, sinc, o);
            if (lane >= o) sinc += u;
        }
        wsum[lane] = sinc - s;
        if (lane == 31) g_rowptr[n] = sinc;
    }
    __syncthreads();
    if (t < nb) g_boff[t] = wsum[w] + inc2 - v2;
    if (t == 0) g_done = 0;        // reset for next replay (deterministic)
}

// -------- phase 3: add block offsets; seed g_fill --------
__global__ void k_scan3(int n) {
    int i = blockIdx.x * blockDim.x + threadIdx.x;
    if (i < n) {
        int r = g_rowptr[i] + g_boff[i / SCB];
        g_rowptr[i] = r;
        g_fill[i]   = r;
    }
}

// -------- CSR fill: cursor atomics, 2 edges per thread --------
__global__ void k_fill(const int* __restrict__ ei, int E, int n) {
    int base = 2 * (blockIdx.x * blockDim.x + threadIdx.x);
    if (base >= E) return;
    if (base + 1 < E) {
        int2 s2 = *(const int2*)(ei + base);
        int2 d2 = *(const int2*)(ei + E + base);
        int s0 = ((unsigned)s2.x < (unsigned)n) ? s2.x : 0;
        int s1 = ((unsigned)s2.y < (unsigned)n) ? s2.y : 0;
        int d0 = ((unsigned)d2.x < (unsigned)n) ? d2.x : 0;
        int d1 = ((unsigned)d2.y < (unsigned)n) ? d2.y : 0;
        g_csrc[atomicAdd(&g_fill[d0], 1)] = s0;
        g_csrc[atomicAdd(&g_fill[d1], 1)] = s1;
    } else {
        int s = ei[base], d = ei[E + base];
        if ((unsigned)s >= (unsigned)n || (unsigned)d >= (unsigned)n) { s = 0; d = 0; }
        g_csrc[atomicAdd(&g_fill[d], 1)] = s;
    }
}

// -------- GEMM fp32 in (layer 1), half out, *dinv epilogue --------
template<int K, int MOUT>
__global__ void k_gemmf(const float* __restrict__ X, const float* __restrict__ W,
                        uint2* __restrict__ OUT, int n) {
    constexpr int K4 = K / 4, M4 = MOUT / 4;
    __shared__ float4 Ws[K * M4];
    int tid = threadIdx.x;
    for (int i = tid; i < K * M4; i += blockDim.x)
        Ws[i] = ((const float4*)W)[i];
    __syncthreads();
    int node = blockIdx.x * blockDim.x + tid;
    if (node >= n) return;
    const float4* xr = (const float4*)(X + (size_t)node * K);
    float4 acc[M4];
    #pragma unroll
    for (int m = 0; m < M4; m++) acc[m] = make_float4(0.f, 0.f, 0.f, 0.f);
    #pragma unroll 4
    for (int k4 = 0; k4 < K4; k4++) {
        float4 x4 = __ldg(&xr[k4]);
        #pragma unroll
        for (int m = 0; m < M4; m++) {
            float4 w0 = Ws[(4 * k4 + 0) * M4 + m];
            float4 w1 = Ws[(4 * k4 + 1) * M4 + m];
            float4 w2 = Ws[(4 * k4 + 2) * M4 + m];
            float4 w3 = Ws[(4 * k4 + 3) * M4 + m];
            acc[m].x += x4.x * w0.x + x4.y * w1.x + x4.z * w2.x + x4.w * w3.x;
            acc[m].y += x4.x * w0.y + x4.y * w1.y + x4.z * w2.y + x4.w * w3.y;
            acc[m].z += x4.x * w0.z + x4.y * w1.z + x4.z * w2.z + x4.w * w3.z;
            acc[m].w += x4.x * w0.w + x4.y * w1.w + x4.z * w2.w + x4.w * w3.w;
        }
    }
    float sc = g_dinv[node];
    uint2* orow = OUT + (size_t)node * M4;
    #pragma unroll
    for (int m = 0; m < M4; m++) {
        float4 a = acc[m];
        a.x *= sc; a.y *= sc; a.z *= sc; a.w *= sc;
        orow[m] = pack4(a);
    }
}

// -------- GEMM half in, half out (layer 3: 64->32, *dinv) --------
template<int K, int MOUT>
__global__ void k_gemmh(const uint4* __restrict__ X, const float* __restrict__ W,
                        uint2* __restrict__ OUT, int n) {
    constexpr int C = K / 8, M4 = MOUT / 4;
    __shared__ float4 Ws[K * M4];
    int tid = threadIdx.x;
    for (int i = tid; i < K * M4; i += blockDim.x)
        Ws[i] = ((const float4*)W)[i];
    __syncthreads();
    int node = blockIdx.x * blockDim.x + tid;
    if (node >= n) return;
    const uint4* xr = X + (size_t)node * C;
    float4 acc[M4];
    #pragma unroll
    for (int m = 0; m < M4; m++) acc[m] = make_float4(0.f, 0.f, 0.f, 0.f);
    #pragma unroll
    for (int c = 0; c < C; c++) {
        uint4 u = __ldg(&xr[c]);
        float xk[8];
        float2 f0 = uph(u.x), f1 = uph(u.y), f2 = uph(u.z), f3 = uph(u.w);
        xk[0] = f0.x; xk[1] = f0.y; xk[2] = f1.x; xk[3] = f1.y;
        xk[4] = f2.x; xk[5] = f2.y; xk[6] = f3.x; xk[7] = f3.y;
        #pragma unroll
        for (int kk = 0; kk < 8; kk++) {
            float xv = xk[kk];
            #pragma unroll
            for (int m = 0; m < M4; m++) {
                float4 w = Ws[(8 * c + kk) * M4 + m];
                acc[m].x += xv * w.x; acc[m].y += xv * w.y;
                acc[m].z += xv * w.z; acc[m].w += xv * w.w;
            }
        }
    }
    float sc = g_dinv[node];
    uint2* orow = OUT + (size_t)node * M4;
    #pragma unroll
    for (int m = 0; m < M4; m++) {
        float4 a = acc[m];
        a.x *= sc; a.y *= sc; a.z *= sc; a.w *= sc;
        orow[m] = pack4(a);
    }
}

// -------- warp-per-node half gather (layers 1 & 3 epilogues) --------
template<int F, bool RELU, bool HASB, bool SCALEOUT>
__global__ void k_gatherh(const uint4* __restrict__ src, uint4* __restrict__ dst,
                          const float* __restrict__ bias, int n) {
    constexpr int LPR = F / 8;
    constexpr int EPW = 32 / LPR;
    int wid = (blockIdx.x * blockDim.x + threadIdx.x) >> 5;
    if (wid >= n) return;
    int lane = threadIdx.x & 31;
    int e_l = lane / LPR;
    int g   = lane % LPR;
    int beg = g_rowptr[wid], end = g_rowptr[wid + 1];
    float a0[8] = {0,0,0,0,0,0,0,0};
    float a1[8] = {0,0,0,0,0,0,0,0};
    int j = beg + e_l;
    for (; j + EPW < end; j += 2 * EPW) {
        int s0 = __ldg(&g_csrc[j]);
        int s1 = __ldg(&g_csrc[j + EPW]);
        uint4 u0 = __ldg(&src[(size_t)s0 * LPR + g]);
        uint4 u1 = __ldg(&src[(size_t)s1 * LPR + g]);
        acc8(a0, u0);
        acc8(a1, u1);
    }
    if (j < end) {
        int s0 = __ldg(&g_csrc[j]);
        uint4 u0 = __ldg(&src[(size_t)s0 * LPR + g]);
        acc8(a0, u0);
    }
    #pragma unroll
    for (int q = 0; q < 8; q++) a0[q] += a1[q];
    #pragma unroll
    for (int off = 16; off >= LPR; off >>= 1) {
        #pragma unroll
        for (int q = 0; q < 8; q++)
            a0[q] += __shfl_xor_sync(0xffffffffu, a0[q], off);
    }
    if (lane < LPR) {
        uint4 hv = src[(size_t)wid * LPR + g];
        acc8(a0, hv);
        float di = g_dinv[wid];
        #pragma unroll
        for (int q = 0; q < 8; q++) a0[q] *= di;
        if (HASB) {
            #pragma unroll
            for (int q = 0; q < 8; q++) a0[q] += __ldg(&bias[8 * g + q]);
        }
        if (RELU) {
            #pragma unroll
            for (int q = 0; q < 8; q++) a0[q] = fmaxf(a0[q], 0.f);
        }
        if (SCALEOUT) {
            #pragma unroll
            for (int q = 0; q < 8; q++) a0[q] *= di;
        }
        uint4 o;
        o.x = pack2(a0[0], a0[1]); o.y = pack2(a0[2], a0[3]);
        o.z = pack2(a0[4], a0[5]); o.w = pack2(a0[6], a0[7]);
        dst[(size_t)wid * LPR + g] = o;
    }
}

// -------- FUSED layer 2: warp gathers agg2 (16) then GEMM 16->64 + bias + relu ----
__global__ void k_g2g(const uint4* __restrict__ src, const float* __restrict__ W2,
                      const float* __restrict__ b2, __half* __restrict__ OUT, int n) {
    __shared__ float Ws[16 * 64];   // 4 KB
    int tid = threadIdx.x;
    for (int i = tid; i < 16 * 64; i += blockDim.x) Ws[i] = W2[i];
    __syncthreads();
    int wid = (blockIdx.x * blockDim.x + tid) >> 5;
    if (wid >= n) return;
    int lane = tid & 31;
    int e_l = lane >> 1;            // 16 edge slots
    int g   = lane & 1;             // 2 uint4-lanes per row
    int beg = g_rowptr[wid], end = g_rowptr[wid + 1];
    float a0[8] = {0,0,0,0,0,0,0,0};
    float a1[8] = {0,0,0,0,0,0,0,0};
    int j = beg + e_l;
    for (; j + 16 < end; j += 32) {
        int s0 = __ldg(&g_csrc[j]);
        int s1 = __ldg(&g_csrc[j + 16]);
        uint4 u0 = __ldg(&src[(size_t)s0 * 2 + g]);
        uint4 u1 = __ldg(&src[(size_t)s1 * 2 + g]);
        acc8(a0, u0);
        acc8(a1, u1);
    }
    if (j < end) {
        int s0 = __ldg(&g_csrc[j]);
        uint4 u0 = __ldg(&src[(size_t)s0 * 2 + g]);
        acc8(a0, u0);
    }
    #pragma unroll
    for (int q = 0; q < 8; q++) a0[q] += a1[q];
    #pragma unroll
    for (int off = 16; off >= 2; off >>= 1) {
        #pragma unroll
        for (int q = 0; q < 8; q++)
            a0[q] += __shfl_xor_sync(0xffffffffu, a0[q], off);
    }
    // all lanes now hold class sums for parity g; add self-loop + scale
    uint4 hv = __ldg(&src[(size_t)wid * 2 + g]);
    acc8(a0, hv);
    float di = g_dinv[wid];
    #pragma unroll
    for (int q = 0; q < 8; q++) a0[q] *= di;
    // broadcast the 16 aggregated features to every lane
    float agg[16];
    #pragma unroll
    for (int q = 0; q < 8; q++) {
        agg[q]     = __shfl_sync(0xffffffffu, a0[q], 0);
        agg[8 + q] = __shfl_sync(0xffffffffu, a0[q], 1);
    }
    // GEMM 16->64: lane m computes outputs m and m+32
    float acc1 = __ldg(&b2[lane]);
    float acc2 = __ldg(&b2[lane + 32]);
    #pragma unroll
    for (int k = 0; k < 16; k++) {
        acc1 += agg[k] * Ws[k * 64 + lane];
        acc2 += agg[k] * Ws[k * 64 + lane + 32];
    }
    __half* orow = OUT + (size_t)wid * 64;
    orow[lane]      = __float2half(fmaxf(acc1, 0.f));
    orow[lane + 32] = __float2half(fmaxf(acc2, 0.f));
}

// -------- FUSED mean pool + MLP head (one block per graph) --------
__global__ void k_poolhead(const __half* __restrict__ fsrc, const int* __restrict__ batch,
                           const float* __restrict__ Wa, const float* __restrict__ ba,
                           const float* __restrict__ Wo, const float* __restrict__ bo,
                           float* __restrict__ out, int n) {
    __shared__ int bounds[2];
    __shared__ float sh[256];
    __shared__ float ps[32];
    __shared__ float a[64];
    int g = blockIdx.x;
    int t = threadIdx.x;
    if (t == 0) {
        int lo = 0, hi = n;
        while (lo < hi) { int mid = (lo + hi) >> 1; if (batch[mid] < g) lo = mid + 1; else hi = mid; }
        bounds[0] = lo;
        int lo2 = lo; hi = n;
        while (lo2 < hi) { int mid = (lo2 + hi) >> 1; if (batch[mid] < g + 1) lo2 = mid + 1; else hi = mid; }
        bounds[1] = lo2;
    }
    __syncthreads();
    int beg = bounds[0], cnt = bounds[1] - bounds[0];
    int f = t & 31, p = t >> 5;
    float s = 0.f;
    for (int k = p; k < cnt; k += 8)
        s += __half2float(fsrc[(size_t)(beg + k) * 32 + f]);
    sh[t] = s;
    __syncthreads();
    if (p == 0) {
        float tot = 0.f;
        #pragma unroll
        for (int q = 0; q < 8; q++) tot += sh[q * 32 + f];
        ps[f] = tot / fmaxf((float)cnt, 1.f);
    }
    __syncthreads();
    if (t < 64) {
        float acc = ba[t];
        #pragma unroll
        for (int k = 0; k < 32; k++) acc += ps[k] * Wa[k * 64 + t];
        a[t] = fmaxf(acc, 0.f);
    }
    __syncthreads();
    if (t < 32) {
        float o = bo[t];
        #pragma unroll
        for (int k = 0; k < 64; k++) o += a[k] * Wo[k * 32 + t];
        out[g * 32 + t] = tanhf(o);
    }
}

// ============================================================================
extern "C" void kernel_launch(void* const* d_in, const int* in_sizes, int n_in,
                              void* d_out, int out_size) {
    const float* x     = (const float*)d_in[0];
    const int*   ei    = (const int*)d_in[1];
    const int*   batch = (const int*)d_in[2];
    const float* W1 = (const float*)d_in[3];  const float* b1 = (const float*)d_in[4];
    const float* W2 = (const float*)d_in[5];  const float* b2 = (const float*)d_in[6];
    const float* W3 = (const float*)d_in[7];  const float* b3 = (const float*)d_in[8];
    const float* Wa = (const float*)d_in[9];  const float* ba = (const float*)d_in[10];
    const float* Wo = (const float*)d_in[11]; const float* bo = (const float*)d_in[12];
    float* out = (float*)d_out;

    int N = in_sizes[0] / FIN;
    int E = in_sizes[1] / 2;
    if (N > NMAX) N = NMAX;
    if (E > EMAX) E = EMAX;
    int nb = (N + SCB - 1) / SCB;

    void *pA = nullptr, *pB = nullptr, *pDeg = nullptr;
    cudaGetSymbolAddress(&pA, g_A);
    cudaGetSymbolAddress(&pB, g_B);
    cudaGetSymbolAddress(&pDeg, g_deg);
    uint4* A4 = (uint4*)pA;  uint2* A2 = (uint2*)pA;
    uint4* B4 = (uint4*)pB;  uint2* B2 = (uint2*)pB;

    const int TB = 256;
    auto blocks = [](long long work, int tb) { return (int)((work + tb - 1) / tb); };
    int gw = blocks((long long)N * 32, TB);
    int gn = blocks(N, TB);

    // ---- CSR build + dinv ----
    cudaMemsetAsync(pDeg, 0, (size_t)N * sizeof(int));
    k_prep<<<blocks((E + 1) / 2, TB), TB>>>(ei, E, N);
    k_scan1<<<nb, SCB>>>(N, nb);
    k_scan3<<<gn, TB>>>(N);
    k_fill<<<blocks((E + 1) / 2, TB), TB>>>(ei, E, N);

    // ---- layer 1: z1s = dinv*(x@W1); h1s = dinv*relu(dinv*(Σ z1s) + b1) ----
    k_gemmf<128, 16><<<gn, TB>>>(x, W1, A2, N);
    k_gatherh<16, true, true, true><<<gw, TB>>>(A4, B4, b1, N);

    // ---- layer 2 (fused): h2 = relu((dinv*(Σ h1s))@W2 + b2) ----
    k_g2g<<<gw, TB>>>(B4, W2, b2, (__half*)pA, N);

    // ---- layer 3: z3s = dinv*(h2@W3); h3 = dinv*(Σ z3s) + b3 ----
    k_gemmh<64, 32><<<gn, TB>>>(A4, W3, B2, N);
    k_gatherh<32, false, true, false><<<gw, TB>>>(B4, A4, b3, N);

    // ---- pool + head (fused) ----
    k_poolhead<<<GNUM, 256>>>((const __half*)pA, batch, Wa, ba, Wo, bo, out, N);
}

// round 11
// speedup vs baseline: 2.0869x; 1.0161x over previous
#include <cuda_runtime.h>
#include <cuda_fp16.h>
#include <math.h>

#define NMAX 100000
#define EMAX 3200000
#define GNUM 64
#define FIN  128
#define SCB  1024
#define NBLK ((NMAX + SCB - 1) / SCB)

// -------- device scratch --------
__device__ uint4  g_A[(size_t)NMAX * 8];     // N x (<=64) halfs, ping
__device__ uint4  g_B[(size_t)NMAX * 8];     // pong
__device__ float  g_dinv[NMAX];
__device__ int    g_deg [NMAX];
__device__ int    g_rowptr[NMAX + 1];        // block-local exclusive; [n]=total
__device__ int    g_bsum[NBLK];
__device__ int    g_boff[NBLK];
__device__ int    g_done;
__device__ int    g_rank[EMAX];              // rank of edge within its dst bucket
__device__ int    g_csrc[EMAX];

// -------- rowptr accessor: block-local + block offset --------
__device__ __forceinline__ int rp(int i, int n) {
    return (i < n) ? (g_rowptr[i] + g_boff[i / SCB]) : g_rowptr[n];
}

// -------- half helpers --------
__device__ __forceinline__ float2 uph(unsigned v) {
    __half2 h = *reinterpret_cast<__half2*>(&v);
    return __half22float2(h);
}
__device__ __forceinline__ unsigned pack2(float x, float y) {
    __half2 h = __floats2half2_rn(x, y);
    return *reinterpret_cast<unsigned*>(&h);
}
__device__ __forceinline__ uint2 pack4(float4 a) {
    return make_uint2(pack2(a.x, a.y), pack2(a.z, a.w));
}
__device__ __forceinline__ void acc8(float* a, uint4 u) {
    float2 f0 = uph(u.x), f1 = uph(u.y), f2 = uph(u.z), f3 = uph(u.w);
    a[0] += f0.x; a[1] += f0.y; a[2] += f1.x; a[3] += f1.y;
    a[4] += f2.x; a[5] += f2.y; a[6] += f3.x; a[7] += f3.y;
}

// -------- degree count on dst + per-edge rank (2 edges per thread) --------
__global__ void k_prep(const int* __restrict__ ei, int E, int n) {
    int base = 2 * (blockIdx.x * blockDim.x + threadIdx.x);
    if (base >= E) return;
    if (base + 1 < E) {
        int2 d2 = *(const int2*)(ei + E + base);
        int d0 = ((unsigned)d2.x < (unsigned)n) ? d2.x : 0;
        int d1 = ((unsigned)d2.y < (unsigned)n) ? d2.y : 0;
        int r0 = atomicAdd(&g_deg[d0], 1);
        int r1 = atomicAdd(&g_deg[d1], 1);
        *(int2*)(g_rank + base) = make_int2(r0, r1);
    } else {
        int d = ei[E + base];
        if ((unsigned)d >= (unsigned)n) d = 0;
        g_rank[base] = atomicAdd(&g_deg[d], 1);
    }
}

// -------- scan phase 1 (+dinv), fused phase 2 in last block --------
__global__ void k_scan1(int n, int nb) {
    __shared__ int wsum[32];
    __shared__ bool lastblk;
    int t = threadIdx.x, lane = t & 31, w = t >> 5;
    int i = blockIdx.x * SCB + t;
    int v = (i < n) ? g_deg[i] : 0;
    if (i < n) g_dinv[i] = rsqrtf((float)v + 1.0f);
    int inc = v;
    #pragma unroll
    for (int o = 1; o < 32; o <<= 1) {
        int u = __shfl_up_sync(0xffffffffu, inc, o);
        if (lane >= o) inc += u;
    }
    if (lane == 31) wsum[w] = inc;
    __syncthreads();
    if (w == 0) {
        int s = wsum[lane];
        int sinc = s;
        #pragma unroll
        for (int o = 1; o < 32; o <<= 1) {
            int u = __shfl_up_sync(0xffffffffu, sinc, o);
            if (lane >= o) sinc += u;
        }
        wsum[lane] = sinc - s;
        if (lane == 31) g_bsum[blockIdx.x] = sinc;
    }
    __syncthreads();
    if (i < n) g_rowptr[i] = wsum[w] + inc - v;   // block-local exclusive

    __threadfence();
    if (t == 0) lastblk = (atomicAdd(&g_done, 1) == nb - 1);
    __syncthreads();
    if (!lastblk) return;
    int v2 = (t < nb) ? g_bsum[t] : 0;
    int inc2 = v2;
    #pragma unroll
    for (int o = 1; o < 32; o <<= 1) {
        int u = __shfl_up_sync(0xffffffffu, inc2, o);
        if (lane >= o) inc2 += u;
    }
    __syncthreads();
    if (lane == 31) wsum[w] = inc2;
    __syncthreads();
    if (w == 0) {
        int s = wsum[lane];
        int sinc = s;
        #pragma unroll
        for (int o = 1; o < 32; o <<= 1) {
            int u = __shfl_up_sync(0xffffffffu, sinc, o);
            if (lane >= o) sinc += u;
        }
        wsum[lane] = sinc - s;
        if (lane == 31) g_rowptr[n] = sinc;       // absolute total
    }
    __syncthreads();
    if (t < nb) g_boff[t] = wsum[w] + inc2 - v2;
    if (t == 0) g_done = 0;
}

// -------- CSR fill: NO atomics (rank precomputed), 2 edges per thread --------
__global__ void k_fill(const int* __restrict__ ei, int E, int n) {
    int base = 2 * (blockIdx.x * blockDim.x + threadIdx.x);
    if (base >= E) return;
    if (base + 1 < E) {
        int2 s2 = *(const int2*)(ei + base);
        int2 d2 = *(const int2*)(ei + E + base);
        int2 r2 = *(const int2*)(g_rank + base);
        int s0 = ((unsigned)s2.x < (unsigned)n) ? s2.x : 0;
        int s1 = ((unsigned)s2.y < (unsigned)n) ? s2.y : 0;
        int d0 = ((unsigned)d2.x < (unsigned)n) ? d2.x : 0;
        int d1 = ((unsigned)d2.y < (unsigned)n) ? d2.y : 0;
        g_csrc[rp(d0, n) + r2.x] = s0;
        g_csrc[rp(d1, n) + r2.y] = s1;
    } else {
        int s = ei[base], d = ei[E + base];
        if ((unsigned)s >= (unsigned)n || (unsigned)d >= (unsigned)n) { s = 0; d = 0; }
        g_csrc[rp(d, n) + g_rank[base]] = s;
    }
}

// -------- GEMM fp32 in (layer 1), half out, *dinv epilogue --------
template<int K, int MOUT>
__global__ void k_gemmf(const float* __restrict__ X, const float* __restrict__ W,
                        uint2* __restrict__ OUT, int n) {
    constexpr int K4 = K / 4, M4 = MOUT / 4;
    __shared__ float4 Ws[K * M4];
    int tid = threadIdx.x;
    for (int i = tid; i < K * M4; i += blockDim.x)
        Ws[i] = ((const float4*)W)[i];
    __syncthreads();
    int node = blockIdx.x * blockDim.x + tid;
    if (node >= n) return;
    const float4* xr = (const float4*)(X + (size_t)node * K);
    float4 acc[M4];
    #pragma unroll
    for (int m = 0; m < M4; m++) acc[m] = make_float4(0.f, 0.f, 0.f, 0.f);
    #pragma unroll 4
    for (int k4 = 0; k4 < K4; k4++) {
        float4 x4 = __ldg(&xr[k4]);
        #pragma unroll
        for (int m = 0; m < M4; m++) {
            float4 w0 = Ws[(4 * k4 + 0) * M4 + m];
            float4 w1 = Ws[(4 * k4 + 1) * M4 + m];
            float4 w2 = Ws[(4 * k4 + 2) * M4 + m];
            float4 w3 = Ws[(4 * k4 + 3) * M4 + m];
            acc[m].x += x4.x * w0.x + x4.y * w1.x + x4.z * w2.x + x4.w * w3.x;
            acc[m].y += x4.x * w0.y + x4.y * w1.y + x4.z * w2.y + x4.w * w3.y;
            acc[m].z += x4.x * w0.z + x4.y * w1.z + x4.z * w2.z + x4.w * w3.z;
            acc[m].w += x4.x * w0.w + x4.y * w1.w + x4.z * w2.w + x4.w * w3.w;
        }
    }
    float sc = g_dinv[node];
    uint2* orow = OUT + (size_t)node * M4;
    #pragma unroll
    for (int m = 0; m < M4; m++) {
        float4 a = acc[m];
        a.x *= sc; a.y *= sc; a.z *= sc; a.w *= sc;
        orow[m] = pack4(a);
    }
}

// -------- GEMM half in, half out (layer 3: 64->32, *dinv) --------
template<int K, int MOUT>
__global__ void k_gemmh(const uint4* __restrict__ X, const float* __restrict__ W,
                        uint2* __restrict__ OUT, int n) {
    constexpr int C = K / 8, M4 = MOUT / 4;
    __shared__ float4 Ws[K * M4];
    int tid = threadIdx.x;
    for (int i = tid; i < K * M4; i += blockDim.x)
        Ws[i] = ((const float4*)W)[i];
    __syncthreads();
    int node = blockIdx.x * blockDim.x + tid;
    if (node >= n) return;
    const uint4* xr = X + (size_t)node * C;
    float4 acc[M4];
    #pragma unroll
    for (int m = 0; m < M4; m++) acc[m] = make_float4(0.f, 0.f, 0.f, 0.f);
    #pragma unroll
    for (int c = 0; c < C; c++) {
        uint4 u = __ldg(&xr[c]);
        float xk[8];
        float2 f0 = uph(u.x), f1 = uph(u.y), f2 = uph(u.z), f3 = uph(u.w);
        xk[0] = f0.x; xk[1] = f0.y; xk[2] = f1.x; xk[3] = f1.y;
        xk[4] = f2.x; xk[5] = f2.y; xk[6] = f3.x; xk[7] = f3.y;
        #pragma unroll
        for (int kk = 0; kk < 8; kk++) {
            float xv = xk[kk];
            #pragma unroll
            for (int m = 0; m < M4; m++) {
                float4 w = Ws[(8 * c + kk) * M4 + m];
                acc[m].x += xv * w.x; acc[m].y += xv * w.y;
                acc[m].z += xv * w.z; acc[m].w += xv * w.w;
            }
        }
    }
    float sc = g_dinv[node];
    uint2* orow = OUT + (size_t)node * M4;
    #pragma unroll
    for (int m = 0; m < M4; m++) {
        float4 a = acc[m];
        a.x *= sc; a.y *= sc; a.z *= sc; a.w *= sc;
        orow[m] = pack4(a);
    }
}

// -------- warp-per-node half gather (layers 1 & 3 epilogues) --------
template<int F, bool RELU, bool HASB, bool SCALEOUT>
__global__ void k_gatherh(const uint4* __restrict__ src, uint4* __restrict__ dst,
                          const float* __restrict__ bias, int n) {
    constexpr int LPR = F / 8;
    constexpr int EPW = 32 / LPR;
    int wid = (blockIdx.x * blockDim.x + threadIdx.x) >> 5;
    if (wid >= n) return;
    int lane = threadIdx.x & 31;
    int e_l = lane / LPR;
    int g   = lane % LPR;
    int beg = rp(wid, n), end = rp(wid + 1, n);
    float a0[8] = {0,0,0,0,0,0,0,0};
    float a1[8] = {0,0,0,0,0,0,0,0};
    int j = beg + e_l;
    for (; j + EPW < end; j += 2 * EPW) {
        int s0 = __ldg(&g_csrc[j]);
        int s1 = __ldg(&g_csrc[j + EPW]);
        uint4 u0 = __ldg(&src[(size_t)s0 * LPR + g]);
        uint4 u1 = __ldg(&src[(size_t)s1 * LPR + g]);
        acc8(a0, u0);
        acc8(a1, u1);
    }
    if (j < end) {
        int s0 = __ldg(&g_csrc[j]);
        uint4 u0 = __ldg(&src[(size_t)s0 * LPR + g]);
        acc8(a0, u0);
    }
    #pragma unroll
    for (int q = 0; q < 8; q++) a0[q] += a1[q];
    #pragma unroll
    for (int off = 16; off >= LPR; off >>= 1) {
        #pragma unroll
        for (int q = 0; q < 8; q++)
            a0[q] += __shfl_xor_sync(0xffffffffu, a0[q], off);
    }
    if (lane < LPR) {
        uint4 hv = src[(size_t)wid * LPR + g];
        acc8(a0, hv);
        float di = g_dinv[wid];
        #pragma unroll
        for (int q = 0; q < 8; q++) a0[q] *= di;
        if (HASB) {
            #pragma unroll
            for (int q = 0; q < 8; q++) a0[q] += __ldg(&bias[8 * g + q]);
        }
        if (RELU) {
            #pragma unroll
            for (int q = 0; q < 8; q++) a0[q] = fmaxf(a0[q], 0.f);
        }
        if (SCALEOUT) {
            #pragma unroll
            for (int q = 0; q < 8; q++) a0[q] *= di;
        }
        uint4 o;
        o.x = pack2(a0[0], a0[1]); o.y = pack2(a0[2], a0[3]);
        o.z = pack2(a0[4], a0[5]); o.w = pack2(a0[6], a0[7]);
        dst[(size_t)wid * LPR + g] = o;
    }
}

// -------- FUSED layer 2: warp gathers agg2 (16) then GEMM 16->64 + bias + relu ----
__global__ void k_g2g(const uint4* __restrict__ src, const float* __restrict__ W2,
                      const float* __restrict__ b2, __half* __restrict__ OUT, int n) {
    __shared__ float Ws[16 * 64];
    int tid = threadIdx.x;
    for (int i = tid; i < 16 * 64; i += blockDim.x) Ws[i] = W2[i];
    __syncthreads();
    int wid = (blockIdx.x * blockDim.x + tid) >> 5;
    if (wid >= n) return;
    int lane = tid & 31;
    int e_l = lane >> 1;
    int g   = lane & 1;
    int beg = rp(wid, n), end = rp(wid + 1, n);
    float a0[8] = {0,0,0,0,0,0,0,0};
    float a1[8] = {0,0,0,0,0,0,0,0};
    int j = beg + e_l;
    for (; j + 16 < end; j += 32) {
        int s0 = __ldg(&g_csrc[j]);
        int s1 = __ldg(&g_csrc[j + 16]);
        uint4 u0 = __ldg(&src[(size_t)s0 * 2 + g]);
        uint4 u1 = __ldg(&src[(size_t)s1 * 2 + g]);
        acc8(a0, u0);
        acc8(a1, u1);
    }
    if (j < end) {
        int s0 = __ldg(&g_csrc[j]);
        uint4 u0 = __ldg(&src[(size_t)s0 * 2 + g]);
        acc8(a0, u0);
    }
    #pragma unroll
    for (int q = 0; q < 8; q++) a0[q] += a1[q];
    #pragma unroll
    for (int off = 16; off >= 2; off >>= 1) {
        #pragma unroll
        for (int q = 0; q < 8; q++)
            a0[q] += __shfl_xor_sync(0xffffffffu, a0[q], off);
    }
    uint4 hv = __ldg(&src[(size_t)wid * 2 + g]);
    acc8(a0, hv);
    float di = g_dinv[wid];
    #pragma unroll
    for (int q = 0; q < 8; q++) a0[q] *= di;
    float agg[16];
    #pragma unroll
    for (int q = 0; q < 8; q++) {
        agg[q]     = __shfl_sync(0xffffffffu, a0[q], 0);
        agg[8 + q] = __shfl_sync(0xffffffffu, a0[q], 1);
    }
    float acc1 = __ldg(&b2[lane]);
    float acc2 = __ldg(&b2[lane + 32]);
    #pragma unroll
    for (int k = 0; k < 16; k++) {
        acc1 += agg[k] * Ws[k * 64 + lane];
        acc2 += agg[k] * Ws[k * 64 + lane + 32];
    }
    __half* orow = OUT + (size_t)wid * 64;
    orow[lane]      = __float2half(fmaxf(acc1, 0.f));
    orow[lane + 32] = __float2half(fmaxf(acc2, 0.f));
}

// -------- FUSED mean pool + MLP head --------
__global__ void k_poolhead(const __half* __restrict__ fsrc, const int* __restrict__ batch,
                           const float* __restrict__ Wa, const float* __restrict__ ba,
                           const float* __restrict__ Wo, const float* __restrict__ bo,
                           float* __restrict__ out, int n) {
    __shared__ int bounds[2];
    __shared__ float sh[256];
    __shared__ float ps[32];
    __shared__ float a[64];
    int g = blockIdx.x;
    int t = threadIdx.x;
    if (t == 0) {
        int lo = 0, hi = n;
        while (lo < hi) { int mid = (lo + hi) >> 1; if (batch[mid] < g) lo = mid + 1; else hi = mid; }
        bounds[0] = lo;
        int lo2 = lo; hi = n;
        while (lo2 < hi) { int mid = (lo2 + hi) >> 1; if (batch[mid] < g + 1) lo2 = mid + 1; else hi = mid; }
        bounds[1] = lo2;
    }
    __syncthreads();
    int beg = bounds[0], cnt = bounds[1] - bounds[0];
    int f = t & 31, p = t >> 5;
    float s = 0.f;
    for (int k = p; k < cnt; k += 8)
        s += __half2float(fsrc[(size_t)(beg + k) * 32 + f]);
    sh[t] = s;
    __syncthreads();
    if (p == 0) {
        float tot = 0.f;
        #pragma unroll
        for (int q = 0; q < 8; q++) tot += sh[q * 32 + f];
        ps[f] = tot / fmaxf((float)cnt, 1.f);
    }
    __syncthreads();
    if (t < 64) {
        float acc = ba[t];
        #pragma unroll
        for (int k = 0; k < 32; k++) acc += ps[k] * Wa[k * 64 + t];
        a[t] = fmaxf(acc, 0.f);
    }
    __syncthreads();
    if (t < 32) {
        float o = bo[t];
        #pragma unroll
        for (int k = 0; k < 64; k++) o += a[k] * Wo[k * 32 + t];
        out[g * 32 + t] = tanhf(o);
    }
}

// ============================================================================
extern "C" void kernel_launch(void* const* d_in, const int* in_sizes, int n_in,
                              void* d_out, int out_size) {
    const float* x     = (const float*)d_in[0];
    const int*   ei    = (const int*)d_in[1];
    const int*   batch = (const int*)d_in[2];
    const float* W1 = (const float*)d_in[3];  const float* b1 = (const float*)d_in[4];
    const float* W2 = (const float*)d_in[5];  const float* b2 = (const float*)d_in[6];
    const float* W3 = (const float*)d_in[7];  const float* b3 = (const float*)d_in[8];
    const float* Wa = (const float*)d_in[9];  const float* ba = (const float*)d_in[10];
    const float* Wo = (const float*)d_in[11]; const float* bo = (const float*)d_in[12];
    float* out = (float*)d_out;

    int N = in_sizes[0] / FIN;
    int E = in_sizes[1] / 2;
    if (N > NMAX) N = NMAX;
    if (E > EMAX) E = EMAX;
    int nb = (N + SCB - 1) / SCB;

    void *pA = nullptr, *pB = nullptr, *pDeg = nullptr;
    cudaGetSymbolAddress(&pA, g_A);
    cudaGetSymbolAddress(&pB, g_B);
    cudaGetSymbolAddress(&pDeg, g_deg);
    uint4* A4 = (uint4*)pA;  uint2* A2 = (uint2*)pA;
    uint4* B4 = (uint4*)pB;  uint2* B2 = (uint2*)pB;

    const int TB = 256;
    auto blocks = [](long long work, int tb) { return (int)((work + tb - 1) / tb); };
    int gw = blocks((long long)N * 32, TB);
    int gn = blocks(N, TB);

    // ---- CSR build + dinv ----
    cudaMemsetAsync(pDeg, 0, (size_t)N * sizeof(int));
    k_prep<<<blocks((E + 1) / 2, TB), TB>>>(ei, E, N);
    k_scan1<<<nb, SCB>>>(N, nb);
    k_fill<<<blocks((E + 1) / 2, TB), TB>>>(ei, E, N);

    // ---- layer 1 ----
    k_gemmf<128, 16><<<gn, TB>>>(x, W1, A2, N);
    k_gatherh<16, true, true, true><<<gw, TB>>>(A4, B4, b1, N);

    // ---- layer 2 (fused gather+GEMM) ----
    k_g2g<<<gw, TB>>>(B4, W2, b2, (__half*)pA, N);

    // ---- layer 3 ----
    k_gemmh<64, 32><<<gn, TB>>>(A4, W3, B2, N);
    k_gatherh<32, false, true, false><<<gw, TB>>>(B4, A4, b3, N);

    // ---- pool + head (fused) ----
    k_poolhead<<<GNUM, 256>>>((const __half*)pA, batch, Wa, ba, Wo, bo, out, N);
}